// round 4
// baseline (speedup 1.0000x reference)
#include <cuda_runtime.h>
#include <math.h>

// Shapes (fixed)
#define BN   2048
#define NN   256
#define DIN  128
#define DE   64
#define HH   128
#define MD   1664

typedef unsigned long long ull;

// Scratch
__device__ float g_hi[BN * DIN];
__device__ float g_hj[BN * DIN];
__device__ float g_m[(size_t)BN * MD];
__device__ float g_WihT[DIN * 3 * HH];   // [k][384]
__device__ float g_WhhT[DIN * 3 * HH];

// ---- f32x2 helpers --------------------------------------------------------
__device__ __forceinline__ ull ffma2(ull a, ull b, ull c) {
    ull d;
    asm("fma.rn.f32x2 %0, %1, %2, %3;" : "=l"(d) : "l"(a), "l"(b), "l"(c));
    return d;
}
__device__ __forceinline__ ull pk(float a, float b) {
    ull d; asm("mov.b64 %0, {%1,%2};" : "=l"(d) : "f"(a), "f"(b)); return d;
}
__device__ __forceinline__ ull dup(float a) {
    ull d; asm("mov.b64 %0, {%1,%1};" : "=l"(d) : "f"(a)); return d;
}
__device__ __forceinline__ void unpk(ull v, float& x, float& y) {
    asm("mov.b64 {%0,%1}, %2;" : "=f"(x), "=f"(y) : "l"(v));
}

// ---------------------------------------------------------------------------
// K0: transpose GRU weights to k-major [k][384]
// ---------------------------------------------------------------------------
__global__ void k0_prep(const float* __restrict__ Wih,
                        const float* __restrict__ Whh) {
    int idx = blockIdx.x * 128 + threadIdx.x;
    if (idx < 384 * 128) {
        int r = idx >> 7, c = idx & 127;
        g_WihT[c * 384 + r] = Wih[idx];
        g_WhhT[c * 384 + r] = Whh[idx];
    }
}

// ---------------------------------------------------------------------------
// K1: hi/hj projections + copy input into g_m[:,0:128]
// ---------------------------------------------------------------------------
__global__ void __launch_bounds__(128) k1_hij(const float* __restrict__ input,
                                              const float* __restrict__ preW) {
    __shared__ float As[16 * 128];
    int t = threadIdx.x;
    int n0 = blockIdx.x * 16;

    for (int s = t; s < 16 * 128; s += 128) {
        float v = input[(size_t)n0 * 128 + s];
        As[s] = v;
        g_m[(size_t)(n0 + (s >> 7)) * MD + (s & 127)] = v;
    }
    __syncthreads();

    float hi[16], hj[16];
#pragma unroll
    for (int r = 0; r < 16; r++) { hi[r] = 0.f; hj[r] = 0.f; }

    for (int e = 0; e < 128; e += 4) {
        float wi0 = preW[(e + 0) * 128 + t];
        float wi1 = preW[(e + 1) * 128 + t];
        float wi2 = preW[(e + 2) * 128 + t];
        float wi3 = preW[(e + 3) * 128 + t];
        float wj0 = preW[(128 + e + 0) * 128 + t];
        float wj1 = preW[(128 + e + 1) * 128 + t];
        float wj2 = preW[(128 + e + 2) * 128 + t];
        float wj3 = preW[(128 + e + 3) * 128 + t];
#pragma unroll
        for (int r = 0; r < 16; r++) {
            const float4 a = *(const float4*)&As[r * 128 + e];
            hi[r] += a.x * wi0 + a.y * wi1 + a.z * wi2 + a.w * wi3;
            hj[r] += a.x * wj0 + a.y * wj1 + a.z * wj2 + a.w * wj3;
        }
    }
#pragma unroll
    for (int r = 0; r < 16; r++) {
        g_hi[(size_t)(n0 + r) * 128 + t] = hi[r];
        g_hj[(size_t)(n0 + r) * 128 + t] = hj[r];
    }
}

// ---------------------------------------------------------------------------
// K2: per-node sparse aggregation (unchanged)
// ---------------------------------------------------------------------------
__global__ void __launch_bounds__(128) k2_agg(const float* __restrict__ adj,
                                              const float* __restrict__ adjf,
                                              const float* __restrict__ preW,
                                              const float* __restrict__ preb) {
    __shared__ float WeS[DE * 128];
    __shared__ float efT[DE * 4];
    __shared__ int   nbr[NN];
    __shared__ int   cnt;

    int t = threadIdx.x;
    int node = blockIdx.x;
    int nbase = (node >> 8) << 8;

    for (int s = t; s < DE * 128; s += 128) WeS[s] = preW[256 * 128 + s];
    if (t == 0) cnt = 0;
    __syncthreads();

    const float* arow = adj + (size_t)node * NN;
    for (int j = t; j < NN; j += 128)
        if (arow[j] > 0.0f) { int p = atomicAdd(&cnt, 1); nbr[p] = j; }
    __syncthreads();

    int deg = cnt;
    float base = g_hi[(size_t)node * 128 + t] + preb[t];
    float s1 = 0.f, s2 = 0.f, mx = -1e30f, mn = 1e30f;
    const float* efb = adjf + (size_t)node * NN * DE;

    for (int p0 = 0; p0 < deg; p0 += 4) {
        int nb = deg - p0; if (nb > 4) nb = 4;
        __syncthreads();
        for (int s = t; s < DE * 4; s += 128) {
            int u = s & 3, e = s >> 2;
            efT[s] = (u < nb) ? efb[(size_t)nbr[p0 + u] * DE + e] : 0.0f;
        }
        __syncthreads();

        float hjv[4];
#pragma unroll
        for (int u = 0; u < 4; u++) {
            int uu = (u < nb) ? u : 0;
            hjv[u] = g_hj[(size_t)(nbase + nbr[p0 + uu]) * 128 + t];
        }

        float e0 = 0.f, e1 = 0.f, e2 = 0.f, e3 = 0.f;
#pragma unroll
        for (int e = 0; e < DE; e++) {
            float w = WeS[e * 128 + t];
            const float4 v = *(const float4*)&efT[e * 4];
            e0 += v.x * w; e1 += v.y * w; e2 += v.z * w; e3 += v.w * w;
        }
        float ev[4] = {e0, e1, e2, e3};
#pragma unroll
        for (int u = 0; u < 4; u++) {
            if (p0 + u < deg) {
                float tv = base + hjv[u] + ev[u];
                s1 += tv; s2 += tv * tv;
                mx = fmaxf(mx, tv); mn = fminf(mn, tv);
            }
        }
    }

    float degf = (float)deg;
    float degc = fmaxf(degf, 1e-5f);
    float mean = s1 / degc;
    float var = s2 / degc - mean * mean;
    if (var < 0.f) var = 0.f;
    float sd = sqrtf(var + 1e-5f);
    float mxo = (deg > 0) ? mx : 0.f;
    float mno = (deg > 0) ? mn : 0.f;
    float slog = logf(degf + 1.0f) / 3.3f;
    float inv = 1.0f / (slog + 1e-5f);

    float* mrow = g_m + (size_t)node * MD;
    mrow[ 128 + t] = mean;        mrow[ 256 + t] = mxo;
    mrow[ 384 + t] = mno;         mrow[ 512 + t] = sd;
    mrow[ 640 + t] = mean * slog; mrow[ 768 + t] = mxo * slog;
    mrow[ 896 + t] = mno * slog;  mrow[1024 + t] = sd * slog;
    mrow[1152 + t] = mean * inv;  mrow[1280 + t] = mxo * inv;
    mrow[1408 + t] = mno * inv;   mrow[1536 + t] = sd * inv;
}

// ---------------------------------------------------------------------------
// K3 v3: col-pair f32x2, plain (non-duplicated) smem, k-split into 2 groups.
// Block: 512 threads, 16 rows x 128 cols. Group g = tid>>8 handles half of k.
// Within group: thread = 1 row x 8 cols (4 f32x2 col-pair accumulators).
// ---------------------------------------------------------------------------
#define KT1  32
#define NT1  26       // 26*32 = 832 = half of MD
#define KTG  8
#define NTG  8        // 8*8 = 64 = half of 128

// smem (floats):
//  [0, 16384)   WBUF (64KB): weight tiles / partial buffers (time-multiplexed)
//  [16384,+1024) As: group g at +g*512, layout [row][32]
//  [17408,+2048) Ys [row][128]
//  [19456,+2048) Xs [row][128]
//  [21504,+2048) Hs [row][128]
#define SMEM_F  23552
#define SMEM_K3 (SMEM_F * 4)

__global__ void __launch_bounds__(512, 1) k3_tail(
        const float* __restrict__ postW, const float* __restrict__ postb,
        const float* __restrict__ mixW,  const float* __restrict__ mixb,
        const float* __restrict__ hidden, float* __restrict__ out) {
    extern __shared__ float sm[];
    float* WBUF = sm;
    float* As   = sm + 16384;
    float* Ys   = sm + 17408;
    float* Xs   = sm + 19456;
    float* Hs   = sm + 21504;

    const int tid  = threadIdx.x;
    const int g    = tid >> 8;       // k-group 0/1
    const int r    = tid & 255;
    const int row  = r >> 4;         // 0..15
    const int col8 = (r & 15) * 8;   // 0,8,...,120
    const int n0   = blockIdx.x * 16;

    float* Wg = WBUF + g * 8192;
    float* Ag = As + g * 512;

    // ---- stage hidden [row][128] (flat, conflict-free) ----
#pragma unroll
    for (int j = 0; j < 4; j++) {
        int idx = tid + j * 512;
        Hs[idx] = hidden[(size_t)n0 * 128 + idx];
    }

    // ======================= phase 1: y1 = m_cat @ post_W ==================
    const float4* pw4 = (const float4*)postW;
    const int kbase0 = g * (NT1 * KT1);    // 0 or 832

    float4 wreg[4];
    float  areg[2];
#pragma unroll
    for (int j = 0; j < 4; j++) wreg[j] = pw4[kbase0 * 32 + r * 4 + j];
#pragma unroll
    for (int j = 0; j < 2; j++) {
        int idx = r + j * 256;
        areg[j] = g_m[(size_t)(n0 + (idx >> 5)) * MD + kbase0 + (idx & 31)];
    }

    ull acc0 = 0, acc1 = 0, acc2 = 0, acc3 = 0;
    for (int tile = 0; tile < NT1; tile++) {
        if (tile) __syncthreads();
#pragma unroll
        for (int j = 0; j < 4; j++) ((float4*)Wg)[r * 4 + j] = wreg[j];
#pragma unroll
        for (int j = 0; j < 2; j++) Ag[r + j * 256] = areg[j];
        __syncthreads();
        if (tile + 1 < NT1) {
            int kb = kbase0 + (tile + 1) * KT1;
#pragma unroll
            for (int j = 0; j < 4; j++) wreg[j] = pw4[kb * 32 + r * 4 + j];
#pragma unroll
            for (int j = 0; j < 2; j++) {
                int idx = r + j * 256;
                areg[j] = g_m[(size_t)(n0 + (idx >> 5)) * MD + kb + (idx & 31)];
            }
        }
#pragma unroll
        for (int kk = 0; kk < KT1; kk++) {
            ull a2 = dup(Ag[row * 32 + kk]);
            float4 w0 = *(const float4*)&Wg[kk * 128 + col8];
            float4 w1 = *(const float4*)&Wg[kk * 128 + col8 + 4];
            acc0 = ffma2(a2, pk(w0.x, w0.y), acc0);
            acc1 = ffma2(a2, pk(w0.z, w0.w), acc1);
            acc2 = ffma2(a2, pk(w1.x, w1.y), acc2);
            acc3 = ffma2(a2, pk(w1.z, w1.w), acc3);
        }
    }

    // prefetch mixW group slice (32KB/group) while reducing
    float4 mreg[8];
#pragma unroll
    for (int j = 0; j < 8; j++) mreg[j] = ((const float4*)mixW)[g * 2048 + r * 8 + j];

    // ---- reduce partials across groups, add bias -> Ys ----
    __syncthreads();                       // WBUF free, all compute done
    float* Ypart = WBUF;                   // 2048 floats
    if (g == 1) {
        float x0, x1, x2, x3, x4, x5, x6, x7;
        unpk(acc0, x0, x1); unpk(acc1, x2, x3); unpk(acc2, x4, x5); unpk(acc3, x6, x7);
        *(float4*)&Ypart[row * 128 + col8]     = make_float4(x0, x1, x2, x3);
        *(float4*)&Ypart[row * 128 + col8 + 4] = make_float4(x4, x5, x6, x7);
    }
    __syncthreads();
    if (g == 0) {
        float x[8];
        unpk(acc0, x[0], x[1]); unpk(acc1, x[2], x[3]);
        unpk(acc2, x[4], x[5]); unpk(acc3, x[6], x[7]);
        float4 p0 = *(const float4*)&Ypart[row * 128 + col8];
        float4 p1 = *(const float4*)&Ypart[row * 128 + col8 + 4];
        float pp[8] = {p0.x, p0.y, p0.z, p0.w, p1.x, p1.y, p1.z, p1.w};
#pragma unroll
        for (int i = 0; i < 8; i++) x[i] += pp[i] + postb[col8 + i];
        *(float4*)&Ys[row * 128 + col8]     = make_float4(x[0], x[1], x[2], x[3]);
        *(float4*)&Ys[row * 128 + col8 + 4] = make_float4(x[4], x[5], x[6], x[7]);
    }
    __syncthreads();

    // ======================= phase 2: mix + leaky ==========================
#pragma unroll
    for (int j = 0; j < 8; j++) ((float4*)Wg)[r * 8 + j] = mreg[j];
    __syncthreads();

    ull m0 = 0, m1 = 0, m2 = 0, m3 = 0;
    {
        const int kb = g * 64;
#pragma unroll 8
        for (int kk = 0; kk < 64; kk++) {
            ull a2 = dup(Ys[row * 128 + kb + kk]);
            float4 w0 = *(const float4*)&Wg[kk * 128 + col8];
            float4 w1 = *(const float4*)&Wg[kk * 128 + col8 + 4];
            m0 = ffma2(a2, pk(w0.x, w0.y), m0);
            m1 = ffma2(a2, pk(w0.z, w0.w), m1);
            m2 = ffma2(a2, pk(w1.x, w1.y), m2);
            m3 = ffma2(a2, pk(w1.z, w1.w), m3);
        }
    }
    __syncthreads();
    float* Mpart = WBUF;
    if (g == 1) {
        float x0, x1, x2, x3, x4, x5, x6, x7;
        unpk(m0, x0, x1); unpk(m1, x2, x3); unpk(m2, x4, x5); unpk(m3, x6, x7);
        *(float4*)&Mpart[row * 128 + col8]     = make_float4(x0, x1, x2, x3);
        *(float4*)&Mpart[row * 128 + col8 + 4] = make_float4(x4, x5, x6, x7);
    }
    __syncthreads();
    if (g == 0) {
        float x[8];
        unpk(m0, x[0], x[1]); unpk(m1, x[2], x[3]);
        unpk(m2, x[4], x[5]); unpk(m3, x[6], x[7]);
        float4 p0 = *(const float4*)&Mpart[row * 128 + col8];
        float4 p1 = *(const float4*)&Mpart[row * 128 + col8 + 4];
        float pp[8] = {p0.x, p0.y, p0.z, p0.w, p1.x, p1.y, p1.z, p1.w};
#pragma unroll
        for (int i = 0; i < 8; i++) {
            float y = x[i] + pp[i] + mixb[col8 + i];
            x[i] = (y > 0.f) ? y : 0.01f * y;
        }
        *(float4*)&Xs[row * 128 + col8]     = make_float4(x[0], x[1], x[2], x[3]);
        *(float4*)&Xs[row * 128 + col8 + 4] = make_float4(x[4], x[5], x[6], x[7]);
    }

    // ======================= phase 3: GRU ==================================
    const float4* wiT4 = (const float4*)g_WihT;
    const float4* whT4 = (const float4*)g_WhhT;
    const int kgb = g * 64;

    float4 gi[3], gh[3];
#pragma unroll
    for (int j = 0; j < 3; j++) {
        gi[j] = wiT4[kgb * 96 + r * 3 + j];
        gh[j] = whT4[kgb * 96 + r * 3 + j];
    }

    ull R0=0,R1=0,R2=0,R3=0, Z0=0,Z1=0,Z2=0,Z3=0;
    ull I0=0,I1=0,I2=0,I3=0, H0=0,H1=0,H2=0,H3=0;

    float* WiS = WBUF + g * 8192;          // 3072 floats
    float* WhS = WiS + 3072;

    for (int tg = 0; tg < NTG; tg++) {
        __syncthreads();                   // prev readers done / Xs ready (tg==0)
#pragma unroll
        for (int j = 0; j < 3; j++) {
            ((float4*)WiS)[r * 3 + j] = gi[j];
            ((float4*)WhS)[r * 3 + j] = gh[j];
        }
        __syncthreads();
        if (tg + 1 < NTG) {
            int kb = (kgb + (tg + 1) * KTG) * 96;
#pragma unroll
            for (int j = 0; j < 3; j++) {
                gi[j] = wiT4[kb + r * 3 + j];
                gh[j] = whT4[kb + r * 3 + j];
            }
        }
#pragma unroll
        for (int kk = 0; kk < KTG; kk++) {
            int k = kgb + tg * KTG + kk;
            ull x2 = dup(Xs[row * 128 + k]);
            ull h2 = dup(Hs[row * 128 + k]);
            int b = kk * 384;
            float4 wr0 = *(const float4*)&WiS[b + col8];
            float4 wr1 = *(const float4*)&WiS[b + col8 + 4];
            float4 wz0 = *(const float4*)&WiS[b + 128 + col8];
            float4 wz1 = *(const float4*)&WiS[b + 128 + col8 + 4];
            float4 wn0 = *(const float4*)&WiS[b + 256 + col8];
            float4 wn1 = *(const float4*)&WiS[b + 256 + col8 + 4];
            float4 vr0 = *(const float4*)&WhS[b + col8];
            float4 vr1 = *(const float4*)&WhS[b + col8 + 4];
            float4 vz0 = *(const float4*)&WhS[b + 128 + col8];
            float4 vz1 = *(const float4*)&WhS[b + 128 + col8 + 4];
            float4 vn0 = *(const float4*)&WhS[b + 256 + col8];
            float4 vn1 = *(const float4*)&WhS[b + 256 + col8 + 4];
            R0 = ffma2(x2, pk(wr0.x, wr0.y), R0); R0 = ffma2(h2, pk(vr0.x, vr0.y), R0);
            R1 = ffma2(x2, pk(wr0.z, wr0.w), R1); R1 = ffma2(h2, pk(vr0.z, vr0.w), R1);
            R2 = ffma2(x2, pk(wr1.x, wr1.y), R2); R2 = ffma2(h2, pk(vr1.x, vr1.y), R2);
            R3 = ffma2(x2, pk(wr1.z, wr1.w), R3); R3 = ffma2(h2, pk(vr1.z, vr1.w), R3);
            Z0 = ffma2(x2, pk(wz0.x, wz0.y), Z0); Z0 = ffma2(h2, pk(vz0.x, vz0.y), Z0);
            Z1 = ffma2(x2, pk(wz0.z, wz0.w), Z1); Z1 = ffma2(h2, pk(vz0.z, vz0.w), Z1);
            Z2 = ffma2(x2, pk(wz1.x, wz1.y), Z2); Z2 = ffma2(h2, pk(vz1.x, vz1.y), Z2);
            Z3 = ffma2(x2, pk(wz1.z, wz1.w), Z3); Z3 = ffma2(h2, pk(vz1.z, vz1.w), Z3);
            I0 = ffma2(x2, pk(wn0.x, wn0.y), I0);
            I1 = ffma2(x2, pk(wn0.z, wn0.w), I1);
            I2 = ffma2(x2, pk(wn1.x, wn1.y), I2);
            I3 = ffma2(x2, pk(wn1.z, wn1.w), I3);
            H0 = ffma2(h2, pk(vn0.x, vn0.y), H0);
            H1 = ffma2(h2, pk(vn0.z, vn0.w), H1);
            H2 = ffma2(h2, pk(vn1.x, vn1.y), H2);
            H3 = ffma2(h2, pk(vn1.z, vn1.w), H3);
        }
    }

    // ---- cross-group gate reduction + epilogue ----
    __syncthreads();
    float* Gp = WBUF;                       // 4 x 2048 floats (32KB)
    if (g == 1) {
        ull rr[4] = {R0, R1, R2, R3};
        ull zz[4] = {Z0, Z1, Z2, Z3};
        ull ii[4] = {I0, I1, I2, I3};
        ull hh[4] = {H0, H1, H2, H3};
#pragma unroll
        for (int p = 0; p < 4; p++) {
            float a, b;
            unpk(rr[p], a, b); *(float2*)&Gp[          row * 128 + col8 + 2 * p] = make_float2(a, b);
            unpk(zz[p], a, b); *(float2*)&Gp[2048 +    row * 128 + col8 + 2 * p] = make_float2(a, b);
            unpk(ii[p], a, b); *(float2*)&Gp[4096 +    row * 128 + col8 + 2 * p] = make_float2(a, b);
            unpk(hh[p], a, b); *(float2*)&Gp[6144 +    row * 128 + col8 + 2 * p] = make_float2(a, b);
        }
    }
    __syncthreads();
    if (g == 0) {
        float Rv[8], Zv[8], Iv[8], Hv[8];
        unpk(R0, Rv[0], Rv[1]); unpk(R1, Rv[2], Rv[3]); unpk(R2, Rv[4], Rv[5]); unpk(R3, Rv[6], Rv[7]);
        unpk(Z0, Zv[0], Zv[1]); unpk(Z1, Zv[2], Zv[3]); unpk(Z2, Zv[4], Zv[5]); unpk(Z3, Zv[6], Zv[7]);
        unpk(I0, Iv[0], Iv[1]); unpk(I1, Iv[2], Iv[3]); unpk(I2, Iv[4], Iv[5]); unpk(I3, Iv[6], Iv[7]);
        unpk(H0, Hv[0], Hv[1]); unpk(H1, Hv[2], Hv[3]); unpk(H2, Hv[4], Hv[5]); unpk(H3, Hv[6], Hv[7]);
        float o[8];
#pragma unroll
        for (int i = 0; i < 8; i++) {
            int c = col8 + i;
            float rg = Rv[i] + Gp[row * 128 + c];
            float zg = Zv[i] + Gp[2048 + row * 128 + c];
            float ig = Iv[i] + Gp[4096 + row * 128 + c];
            float hg = Hv[i] + Gp[6144 + row * 128 + c];
            float rs = 1.0f / (1.0f + expf(-rg));
            float zs = 1.0f / (1.0f + expf(-zg));
            float nn = tanhf(ig + rs * hg);
            float hv = Hs[row * 128 + c];
            o[i] = (1.0f - zs) * nn + zs * hv;
        }
        *(float4*)&out[(size_t)(n0 + row) * 128 + col8]     = make_float4(o[0], o[1], o[2], o[3]);
        *(float4*)&out[(size_t)(n0 + row) * 128 + col8 + 4] = make_float4(o[4], o[5], o[6], o[7]);
    }
}

// ---------------------------------------------------------------------------
extern "C" void kernel_launch(void* const* d_in, const int* in_sizes, int n_in,
                              void* d_out, int out_size) {
    const float* input  = (const float*)d_in[0];
    const float* adj    = (const float*)d_in[1];
    const float* adjf   = (const float*)d_in[2];
    const float* hidden = (const float*)d_in[3];
    const float* preW   = (const float*)d_in[4];
    const float* preb   = (const float*)d_in[5];
    const float* postW  = (const float*)d_in[6];
    const float* postb  = (const float*)d_in[7];
    const float* mixW   = (const float*)d_in[8];
    const float* mixb   = (const float*)d_in[9];
    const float* Wih    = (const float*)d_in[10];
    const float* Whh    = (const float*)d_in[11];
    float* out = (float*)d_out;

    cudaFuncSetAttribute(k3_tail, cudaFuncAttributeMaxDynamicSharedMemorySize, SMEM_K3);

    k0_prep<<<384, 128>>>(Wih, Whh);
    k1_hij<<<128, 128>>>(input, preW);
    k2_agg<<<BN, 128>>>(adj, adjf, preW, preb);
    k3_tail<<<128, 512, SMEM_K3>>>(postW, postb, mixW, mixb, hidden, out);
}

// round 5
// speedup vs baseline: 1.6192x; 1.6192x over previous
#include <cuda_runtime.h>
#include <math.h>

#define BN 2048
#define NN 256
#define MD 1664

typedef unsigned long long ull;

__device__ float g_hi[BN * 128];
__device__ float g_hj[BN * 128];
__device__ float g_m[(size_t)BN * MD];
__device__ float g_part[4][BN][128];     // post-GEMM k-split partials
__device__ float g_WihT[128 * 384];      // [k][384]
__device__ float g_WhhT[128 * 384];

__device__ __forceinline__ ull ffma2(ull a, ull b, ull c) {
    ull d;
    asm("fma.rn.f32x2 %0, %1, %2, %3;" : "=l"(d) : "l"(a), "l"(b), "l"(c));
    return d;
}
__device__ __forceinline__ ull dup(float a) {
    ull d; asm("mov.b64 %0, {%1,%1};" : "=l"(d) : "f"(a)); return d;
}
__device__ __forceinline__ void unpk(ull v, float& x, float& y) {
    asm("mov.b64 {%0,%1}, %2;" : "=f"(x), "=f"(y) : "l"(v));
}

// ---------------------------------------------------------------------------
// K0: GRU weight transpose -> [k][384]
// ---------------------------------------------------------------------------
__global__ void k0_prep(const float* __restrict__ Wih,
                        const float* __restrict__ Whh) {
    int idx = blockIdx.x * 128 + threadIdx.x;
    int r = idx >> 7, c = idx & 127;
    g_WihT[c * 384 + r] = Wih[idx];
    g_WhhT[c * 384 + r] = Whh[idx];
}

// ---------------------------------------------------------------------------
// K1: hi/hj projections + input -> g_m[:,0:128]
// ---------------------------------------------------------------------------
__global__ void __launch_bounds__(128) k1_hij(const float* __restrict__ input,
                                              const float* __restrict__ preW) {
    __shared__ float As[16 * 128];
    int t = threadIdx.x;
    int n0 = blockIdx.x * 16;

    for (int s = t; s < 16 * 128; s += 128) {
        float v = input[(size_t)n0 * 128 + s];
        As[s] = v;
        g_m[(size_t)(n0 + (s >> 7)) * MD + (s & 127)] = v;
    }
    __syncthreads();

    float hi[16], hj[16];
#pragma unroll
    for (int r = 0; r < 16; r++) { hi[r] = 0.f; hj[r] = 0.f; }

    for (int e = 0; e < 128; e += 4) {
        float wi0 = preW[(e + 0) * 128 + t];
        float wi1 = preW[(e + 1) * 128 + t];
        float wi2 = preW[(e + 2) * 128 + t];
        float wi3 = preW[(e + 3) * 128 + t];
        float wj0 = preW[(128 + e + 0) * 128 + t];
        float wj1 = preW[(128 + e + 1) * 128 + t];
        float wj2 = preW[(128 + e + 2) * 128 + t];
        float wj3 = preW[(128 + e + 3) * 128 + t];
#pragma unroll
        for (int r = 0; r < 16; r++) {
            const float4 a = *(const float4*)&As[r * 128 + e];
            hi[r] += a.x * wi0 + a.y * wi1 + a.z * wi2 + a.w * wi3;
            hj[r] += a.x * wj0 + a.y * wj1 + a.z * wj2 + a.w * wj3;
        }
    }
#pragma unroll
    for (int r = 0; r < 16; r++) {
        g_hi[(size_t)(n0 + r) * 128 + t] = hi[r];
        g_hj[(size_t)(n0 + r) * 128 + t] = hj[r];
    }
}

// ---------------------------------------------------------------------------
// K2: per-node sparse aggregation -> g_m[:,128:1664]
// ---------------------------------------------------------------------------
__global__ void __launch_bounds__(128) k2_agg(const float* __restrict__ adj,
                                              const float* __restrict__ adjf,
                                              const float* __restrict__ preW,
                                              const float* __restrict__ preb) {
    __shared__ float WeS[64 * 128];
    __shared__ float efT[64 * 4];
    __shared__ int   nbr[NN];
    __shared__ int   cnt;

    int t = threadIdx.x;
    int node = blockIdx.x;
    int nbase = (node >> 8) << 8;

    for (int s = t; s < 64 * 128; s += 128) WeS[s] = preW[256 * 128 + s];
    if (t == 0) cnt = 0;
    __syncthreads();

    const float* arow = adj + (size_t)node * NN;
    for (int j = t; j < NN; j += 128)
        if (arow[j] > 0.0f) { int p = atomicAdd(&cnt, 1); nbr[p] = j; }
    __syncthreads();

    int deg = cnt;
    float base = g_hi[(size_t)node * 128 + t] + preb[t];
    float s1 = 0.f, s2 = 0.f, mx = -1e30f, mn = 1e30f;
    const float* efb = adjf + (size_t)node * NN * 64;

    for (int p0 = 0; p0 < deg; p0 += 4) {
        int nb = deg - p0; if (nb > 4) nb = 4;
        __syncthreads();
        for (int s = t; s < 64 * 4; s += 128) {
            int u = s & 3, e = s >> 2;
            efT[s] = (u < nb) ? efb[(size_t)nbr[p0 + u] * 64 + e] : 0.0f;
        }
        __syncthreads();

        float hjv[4];
#pragma unroll
        for (int u = 0; u < 4; u++) {
            int uu = (u < nb) ? u : 0;
            hjv[u] = g_hj[(size_t)(nbase + nbr[p0 + uu]) * 128 + t];
        }

        float e0 = 0.f, e1 = 0.f, e2 = 0.f, e3 = 0.f;
#pragma unroll
        for (int e = 0; e < 64; e++) {
            float w = WeS[e * 128 + t];
            const float4 v = *(const float4*)&efT[e * 4];
            e0 += v.x * w; e1 += v.y * w; e2 += v.z * w; e3 += v.w * w;
        }
        float ev[4] = {e0, e1, e2, e3};
#pragma unroll
        for (int u = 0; u < 4; u++) {
            if (p0 + u < deg) {
                float tv = base + hjv[u] + ev[u];
                s1 += tv; s2 += tv * tv;
                mx = fmaxf(mx, tv); mn = fminf(mn, tv);
            }
        }
    }

    float degf = (float)deg;
    float degc = fmaxf(degf, 1e-5f);
    float mean = s1 / degc;
    float var = s2 / degc - mean * mean;
    if (var < 0.f) var = 0.f;
    float sd = sqrtf(var + 1e-5f);
    float mxo = (deg > 0) ? mx : 0.f;
    float mno = (deg > 0) ? mn : 0.f;
    float slog = logf(degf + 1.0f) / 3.3f;
    float inv = 1.0f / (slog + 1e-5f);

    float* mrow = g_m + (size_t)node * MD;
    mrow[ 128 + t] = mean;        mrow[ 256 + t] = mxo;
    mrow[ 384 + t] = mno;         mrow[ 512 + t] = sd;
    mrow[ 640 + t] = mean * slog; mrow[ 768 + t] = mxo * slog;
    mrow[ 896 + t] = mno * slog;  mrow[1024 + t] = sd * slog;
    mrow[1152 + t] = mean * inv;  mrow[1280 + t] = mxo * inv;
    mrow[1408 + t] = mno * inv;   mrow[1536 + t] = sd * inv;
}

// ---------------------------------------------------------------------------
// K3a: y1 partials. grid 256 = 64 row-blocks(32 rows) x 4 k-splits(416 k).
// Warp = 32 rows x 8 cols, all 416 k, zero syncs in hot loop.
// Lane: rg=lane>>2 -> rows rg*4.., cp=lane&3 -> colpair.
// ---------------------------------------------------------------------------
#define KSP 416
#define AST 36                      // padded k-row stride (floats)
#define SMEM_K3A (KSP * AST * 4)    // 59904 B

__global__ void __launch_bounds__(512, 2) k3a_post(const float* __restrict__ postW) {
    extern __shared__ float AsT[];  // [KSP][AST]
    const int tid = threadIdx.x;
    const int w = tid >> 5, lane = tid & 31;
    const int rb = blockIdx.x & 63, kp = blockIdx.x >> 6;
    const int n0 = rb * 32, k0 = kp * KSP;

    // stage A transposed: warp w loads rows 2w, 2w+1
#pragma unroll
    for (int j = 0; j < 2; j++) {
        int r = 2 * w + j;
        const float* src = g_m + (size_t)(n0 + r) * MD + k0;
        for (int k = lane; k < KSP; k += 32)
            AsT[k * AST + r] = src[k];
    }
    __syncthreads();

    const int rg = lane >> 2;
    const int cp = lane & 3;
    const int c0 = w * 8 + cp * 2;
    const float* wp = postW + (size_t)k0 * 128 + c0;

    ull a0 = 0, a1 = 0, a2 = 0, a3 = 0;
#pragma unroll 4
    for (int k = 0; k < KSP; k++) {
        float4 av = *(const float4*)&AsT[k * AST + rg * 4];
        ull wv = *(const ull*)(wp + (size_t)k * 128);
        a0 = ffma2(dup(av.x), wv, a0);
        a1 = ffma2(dup(av.y), wv, a1);
        a2 = ffma2(dup(av.z), wv, a2);
        a3 = ffma2(dup(av.w), wv, a3);
    }
    float* dst = &g_part[kp][n0 + rg * 4][c0];
    *(ull*)(dst)       = a0;
    *(ull*)(dst + 128) = a1;
    *(ull*)(dst + 256) = a2;
    *(ull*)(dst + 384) = a3;
}

// ---------------------------------------------------------------------------
// K3b: reduce partials -> mix+leaky -> GRU. grid 128 x 512 threads, 3 syncs.
// Tiles stored transposed [c][20] for broadcast LDS.64 row-pair reads.
// ---------------------------------------------------------------------------
__global__ void __launch_bounds__(512) k3b_tail(
        const float* __restrict__ postb,
        const float* __restrict__ mixW, const float* __restrict__ mixb,
        const float* __restrict__ hidden, float* __restrict__ out) {
    __shared__ float YsT[128 * 20];
    __shared__ float XsT[128 * 20];
    __shared__ float HsT[128 * 20];
    const int tid = threadIdx.x;
    const int n0 = blockIdx.x * 16;

    // reduce post partials + stage hidden (both transposed)
#pragma unroll
    for (int j = 0; j < 4; j++) {
        int idx = tid + j * 512;
        int r = idx >> 7, c = idx & 127;
        HsT[c * 20 + r] = hidden[(size_t)(n0 + r) * 128 + c];
        float v = postb[c] + g_part[0][n0 + r][c] + g_part[1][n0 + r][c]
                           + g_part[2][n0 + r][c] + g_part[3][n0 + r][c];
        YsT[c * 20 + r] = v;
    }
    __syncthreads();

    const int w = tid >> 5, lane = tid & 31;
    const int rg = lane >> 2;          // rows rg*2, rg*2+1
    const int cp = lane & 3;
    const int c0 = w * 8 + cp * 2;

    // ---- mix + leaky ----
    {
        ull m0 = 0, m1 = 0;
        const float* wp = mixW + c0;
#pragma unroll 4
        for (int k = 0; k < 128; k++) {
            float2 yv = *(const float2*)&YsT[k * 20 + rg * 2];
            ull wv = *(const ull*)(wp + k * 128);
            m0 = ffma2(dup(yv.x), wv, m0);
            m1 = ffma2(dup(yv.y), wv, m1);
        }
        float b0 = mixb[c0], b1 = mixb[c0 + 1];
        float x0, x1, x2, x3;
        unpk(m0, x0, x1); unpk(m1, x2, x3);
        x0 += b0; x1 += b1; x2 += b0; x3 += b1;
        x0 = (x0 > 0.f) ? x0 : 0.01f * x0;
        x1 = (x1 > 0.f) ? x1 : 0.01f * x1;
        x2 = (x2 > 0.f) ? x2 : 0.01f * x2;
        x3 = (x3 > 0.f) ? x3 : 0.01f * x3;
        // (x0,x2) = rows rg*2,rg*2+1 at col c0; (x1,x3) at col c0+1
        *(float2*)&XsT[c0 * 20 + rg * 2]       = make_float2(x0, x2);
        *(float2*)&XsT[(c0 + 1) * 20 + rg * 2] = make_float2(x1, x3);
    }
    __syncthreads();

    // ---- GRU ----
    ull R0 = 0, R1 = 0, Z0 = 0, Z1 = 0, I0 = 0, I1 = 0, N0 = 0, N1 = 0;
    const float* wi = g_WihT + c0;
    const float* wh = g_WhhT + c0;
#pragma unroll 2
    for (int k = 0; k < 128; k++) {
        float2 xv = *(const float2*)&XsT[k * 20 + rg * 2];
        float2 hv = *(const float2*)&HsT[k * 20 + rg * 2];
        const float* wik = wi + k * 384;
        const float* whk = wh + k * 384;
        ull wr = *(const ull*)(wik);
        ull wz = *(const ull*)(wik + 128);
        ull wn = *(const ull*)(wik + 256);
        ull vr = *(const ull*)(whk);
        ull vz = *(const ull*)(whk + 128);
        ull vn = *(const ull*)(whk + 256);
        ull dx0 = dup(xv.x), dx1 = dup(xv.y);
        ull dh0 = dup(hv.x), dh1 = dup(hv.y);
        R0 = ffma2(dx0, wr, R0); R0 = ffma2(dh0, vr, R0);
        R1 = ffma2(dx1, wr, R1); R1 = ffma2(dh1, vr, R1);
        Z0 = ffma2(dx0, wz, Z0); Z0 = ffma2(dh0, vz, Z0);
        Z1 = ffma2(dx1, wz, Z1); Z1 = ffma2(dh1, vz, Z1);
        I0 = ffma2(dx0, wn, I0);
        I1 = ffma2(dx1, wn, I1);
        N0 = ffma2(dh0, vn, N0);
        N1 = ffma2(dh1, vn, N1);
    }

    // epilogue: lane owns rows {rg*2, rg*2+1} x cols {c0, c0+1}
    {
        float Ra, Rb, Rc, Rd, Za, Zb, Zc, Zd;
        float Ia, Ib, Ic, Id, Na, Nb, Nc, Nd;
        unpk(R0, Ra, Rb); unpk(R1, Rc, Rd);   // a:(r0,c0) b:(r0,c1) c:(r1,c0) d:(r1,c1)
        unpk(Z0, Za, Zb); unpk(Z1, Zc, Zd);
        unpk(I0, Ia, Ib); unpk(I1, Ic, Id);
        unpk(N0, Na, Nb); unpk(N1, Nc, Nd);
        float h_a = HsT[c0 * 20 + rg * 2];
        float h_c = HsT[c0 * 20 + rg * 2 + 1];
        float h_b = HsT[(c0 + 1) * 20 + rg * 2];
        float h_d = HsT[(c0 + 1) * 20 + rg * 2 + 1];

        float rv, zv, nv;
        rv = 1.f / (1.f + expf(-Ra)); zv = 1.f / (1.f + expf(-Za));
        nv = tanhf(Ia + rv * Na);
        float oa = (1.f - zv) * nv + zv * h_a;
        rv = 1.f / (1.f + expf(-Rb)); zv = 1.f / (1.f + expf(-Zb));
        nv = tanhf(Ib + rv * Nb);
        float ob = (1.f - zv) * nv + zv * h_b;
        rv = 1.f / (1.f + expf(-Rc)); zv = 1.f / (1.f + expf(-Zc));
        nv = tanhf(Ic + rv * Nc);
        float oc = (1.f - zv) * nv + zv * h_c;
        rv = 1.f / (1.f + expf(-Rd)); zv = 1.f / (1.f + expf(-Zd));
        nv = tanhf(Id + rv * Nd);
        float od = (1.f - zv) * nv + zv * h_d;

        *(float2*)&out[(size_t)(n0 + rg * 2) * 128 + c0]     = make_float2(oa, ob);
        *(float2*)&out[(size_t)(n0 + rg * 2 + 1) * 128 + c0] = make_float2(oc, od);
    }
}

// ---------------------------------------------------------------------------
extern "C" void kernel_launch(void* const* d_in, const int* in_sizes, int n_in,
                              void* d_out, int out_size) {
    const float* input  = (const float*)d_in[0];
    const float* adj    = (const float*)d_in[1];
    const float* adjf   = (const float*)d_in[2];
    const float* hidden = (const float*)d_in[3];
    const float* preW   = (const float*)d_in[4];
    const float* preb   = (const float*)d_in[5];
    const float* postW  = (const float*)d_in[6];
    const float* postb  = (const float*)d_in[7];
    const float* mixW   = (const float*)d_in[8];
    const float* mixb   = (const float*)d_in[9];
    const float* Wih    = (const float*)d_in[10];
    const float* Whh    = (const float*)d_in[11];
    float* out = (float*)d_out;

    cudaFuncSetAttribute(k3a_post, cudaFuncAttributeMaxDynamicSharedMemorySize, SMEM_K3A);

    k0_prep<<<384, 128>>>(Wih, Whh);
    k1_hij<<<128, 128>>>(input, preW);
    k2_agg<<<BN, 128>>>(adj, adjf, preW, preb);
    k3a_post<<<256, 512, SMEM_K3A>>>(postW);
    k3b_tail<<<128, 512>>>(postb, mixW, mixb, hidden, out);
}

// round 6
// speedup vs baseline: 1.6993x; 1.0494x over previous
#include <cuda_runtime.h>
#include <math.h>

#define BN 2048
#define NN 256
#define MD 1664

typedef unsigned long long ull;

__device__ float g_hi[BN * 128];
__device__ float g_hj[BN * 128];
__device__ float g_m[(size_t)BN * MD];
__device__ float g_part[8][BN][128];     // post-GEMM k-split partials
__device__ float g_WihT[128 * 384];      // [k][384]
__device__ float g_WhhT[128 * 384];

__device__ __forceinline__ ull ffma2(ull a, ull b, ull c) {
    ull d;
    asm("fma.rn.f32x2 %0, %1, %2, %3;" : "=l"(d) : "l"(a), "l"(b), "l"(c));
    return d;
}
__device__ __forceinline__ ull dup(float a) {
    ull d; asm("mov.b64 %0, {%1,%1};" : "=l"(d) : "f"(a)); return d;
}
__device__ __forceinline__ void unpk(ull v, float& x, float& y) {
    asm("mov.b64 {%0,%1}, %2;" : "=f"(x), "=f"(y) : "l"(v));
}

// ---------------------------------------------------------------------------
// K0: GRU weight transpose -> [k][384]
// ---------------------------------------------------------------------------
__global__ void k0_prep(const float* __restrict__ Wih,
                        const float* __restrict__ Whh) {
    int idx = blockIdx.x * 128 + threadIdx.x;
    int r = idx >> 7, c = idx & 127;
    g_WihT[c * 384 + r] = Wih[idx];
    g_WhhT[c * 384 + r] = Whh[idx];
}

// ---------------------------------------------------------------------------
// K1: hi/hj projections + input -> g_m[:,0:128].  256 blocks x 8 rows.
// ---------------------------------------------------------------------------
__global__ void __launch_bounds__(128) k1_hij(const float* __restrict__ input,
                                              const float* __restrict__ preW) {
    __shared__ float As[8 * 128];
    int t = threadIdx.x;
    int n0 = blockIdx.x * 8;

    for (int s = t; s < 8 * 128; s += 128) {
        float v = input[(size_t)n0 * 128 + s];
        As[s] = v;
        g_m[(size_t)(n0 + (s >> 7)) * MD + (s & 127)] = v;
    }
    __syncthreads();

    float hi[8], hj[8];
#pragma unroll
    for (int r = 0; r < 8; r++) { hi[r] = 0.f; hj[r] = 0.f; }

    for (int e = 0; e < 128; e += 4) {
        float wi0 = preW[(e + 0) * 128 + t];
        float wi1 = preW[(e + 1) * 128 + t];
        float wi2 = preW[(e + 2) * 128 + t];
        float wi3 = preW[(e + 3) * 128 + t];
        float wj0 = preW[(128 + e + 0) * 128 + t];
        float wj1 = preW[(128 + e + 1) * 128 + t];
        float wj2 = preW[(128 + e + 2) * 128 + t];
        float wj3 = preW[(128 + e + 3) * 128 + t];
#pragma unroll
        for (int r = 0; r < 8; r++) {
            const float4 a = *(const float4*)&As[r * 128 + e];
            hi[r] += a.x * wi0 + a.y * wi1 + a.z * wi2 + a.w * wi3;
            hj[r] += a.x * wj0 + a.y * wj1 + a.z * wj2 + a.w * wj3;
        }
    }
#pragma unroll
    for (int r = 0; r < 8; r++) {
        g_hi[(size_t)(n0 + r) * 128 + t] = hi[r];
        g_hj[(size_t)(n0 + r) * 128 + t] = hj[r];
    }
}

// ---------------------------------------------------------------------------
// K2: per-node sparse aggregation -> g_m[:,128:1664]
// ---------------------------------------------------------------------------
__global__ void __launch_bounds__(128) k2_agg(const float* __restrict__ adj,
                                              const float* __restrict__ adjf,
                                              const float* __restrict__ preW,
                                              const float* __restrict__ preb) {
    __shared__ float WeS[64 * 128];
    __shared__ float efT[64 * 4];
    __shared__ int   nbr[NN];
    __shared__ int   cnt;

    int t = threadIdx.x;
    int node = blockIdx.x;
    int nbase = (node >> 8) << 8;

    for (int s = t; s < 64 * 128; s += 128) WeS[s] = preW[256 * 128 + s];
    if (t == 0) cnt = 0;
    __syncthreads();

    const float* arow = adj + (size_t)node * NN;
    for (int j = t; j < NN; j += 128)
        if (arow[j] > 0.0f) { int p = atomicAdd(&cnt, 1); nbr[p] = j; }
    __syncthreads();

    int deg = cnt;
    float base = g_hi[(size_t)node * 128 + t] + preb[t];
    float s1 = 0.f, s2 = 0.f, mx = -1e30f, mn = 1e30f;
    const float* efb = adjf + (size_t)node * NN * 64;

    for (int p0 = 0; p0 < deg; p0 += 4) {
        int nb = deg - p0; if (nb > 4) nb = 4;
        __syncthreads();
        for (int s = t; s < 64 * 4; s += 128) {
            int u = s & 3, e = s >> 2;
            efT[s] = (u < nb) ? efb[(size_t)nbr[p0 + u] * 64 + e] : 0.0f;
        }
        __syncthreads();

        float hjv[4];
#pragma unroll
        for (int u = 0; u < 4; u++) {
            int uu = (u < nb) ? u : 0;
            hjv[u] = g_hj[(size_t)(nbase + nbr[p0 + uu]) * 128 + t];
        }

        float e0 = 0.f, e1 = 0.f, e2 = 0.f, e3 = 0.f;
#pragma unroll
        for (int e = 0; e < 64; e++) {
            float w = WeS[e * 128 + t];
            const float4 v = *(const float4*)&efT[e * 4];
            e0 += v.x * w; e1 += v.y * w; e2 += v.z * w; e3 += v.w * w;
        }
        float ev[4] = {e0, e1, e2, e3};
#pragma unroll
        for (int u = 0; u < 4; u++) {
            if (p0 + u < deg) {
                float tv = base + hjv[u] + ev[u];
                s1 += tv; s2 += tv * tv;
                mx = fmaxf(mx, tv); mn = fminf(mn, tv);
            }
        }
    }

    float degf = (float)deg;
    float degc = fmaxf(degf, 1e-5f);
    float mean = s1 / degc;
    float var = s2 / degc - mean * mean;
    if (var < 0.f) var = 0.f;
    float sd = sqrtf(var + 1e-5f);
    float mxo = (deg > 0) ? mx : 0.f;
    float mno = (deg > 0) ? mn : 0.f;
    float slog = logf(degf + 1.0f) / 3.3f;
    float inv = 1.0f / (slog + 1e-5f);

    float* mrow = g_m + (size_t)node * MD;
    mrow[ 128 + t] = mean;        mrow[ 256 + t] = mxo;
    mrow[ 384 + t] = mno;         mrow[ 512 + t] = sd;
    mrow[ 640 + t] = mean * slog; mrow[ 768 + t] = mxo * slog;
    mrow[ 896 + t] = mno * slog;  mrow[1024 + t] = sd * slog;
    mrow[1152 + t] = mean * inv;  mrow[1280 + t] = mxo * inv;
    mrow[1408 + t] = mno * inv;   mrow[1536 + t] = sd * inv;
}

// ---------------------------------------------------------------------------
// K3a: y1 partials. grid 256 = 32 rowblocks(64 rows) x 8 ksplits(208 k).
// Warp = 64 rows x 8 cols. Lane = 4 row-pairs x 2 cols (rg=lane>>2, cp=lane&3).
// Row-pairs packed from transposed smem; W software-pipelined from L2.
// ---------------------------------------------------------------------------
#define KSP 208
#define AST 68                       // padded k-row stride (floats); 272B, 16B-aligned
#define SMEM_K3A (KSP * AST * 4)     // 56576 B

__global__ void __launch_bounds__(512, 2) k3a_post(const float* __restrict__ postW) {
    extern __shared__ float AsT[];   // [KSP][AST]: AsT[k*AST + r]
    const int tid = threadIdx.x;
    const int w = tid >> 5, lane = tid & 31;
    const int rb = blockIdx.x & 31, ks = blockIdx.x >> 5;
    const int n0 = rb * 64, k0 = ks * KSP;

    // ---- stage A transposed: thread -> row r = tid>>3, k-chunk j = tid&7 ----
    {
        const int r = tid >> 3;
        const int kt = (tid & 7) * 26;
        const float* src = g_m + (size_t)(n0 + r) * MD + k0 + kt;
#pragma unroll 13
        for (int i = 0; i < 26; i++)
            AsT[(kt + i) * AST + r] = src[i];
    }
    __syncthreads();

    const int rg = lane >> 2;
    const int cp = lane & 3;
    const int c0 = w * 8 + cp * 2;
    const int base = rg * 8;
    const int sel = (rg >= 4) ? 4 : 0;
    const int offA = base + sel;          // first LDS.128 (staggered)
    const int offB = base + 4 - sel;      // second LDS.128

    const float* wp = postW + (size_t)k0 * 128 + c0;

    ull s0 = 0, s1 = 0, s2 = 0, s3 = 0;   // slotA pairs (x2 cols), slotB pairs
    ull t0 = 0, t1 = 0, t2 = 0, t3 = 0;
    // acc layout: s0/s1 = A.x/A.y with col pair packed? No — row-pair packing:
    //   sA0[c] ... use 8 accs: (A.x,A.y,B.x,B.y) x (c0,c0+1)
    ull aA0c0 = 0, aA1c0 = 0, aB0c0 = 0, aB1c0 = 0;
    ull aA0c1 = 0, aA1c1 = 0, aB0c1 = 0, aB1c1 = 0;
    (void)s0; (void)s1; (void)s2; (void)s3; (void)t0; (void)t1; (void)t2; (void)t3;

#define LOADW(buf, b)                                                       \
    {                                                                       \
        _Pragma("unroll")                                                   \
        for (int j = 0; j < 4; j++)                                         \
            buf[j] = *(const ull*)(wp + (size_t)((b) * 4 + j) * 128);       \
    }
#define COMPUTE(b, buf)                                                     \
    {                                                                       \
        _Pragma("unroll")                                                   \
        for (int j = 0; j < 4; j++) {                                       \
            const int k = (b) * 4 + j;                                      \
            ulonglong2 A = *(const ulonglong2*)&AsT[k * AST + offA];        \
            ulonglong2 B = *(const ulonglong2*)&AsT[k * AST + offB];        \
            float wlo, whi; unpk(buf[j], wlo, whi);                         \
            ull w2lo = dup(wlo), w2hi = dup(whi);                           \
            aA0c0 = ffma2(A.x, w2lo, aA0c0);                                \
            aA1c0 = ffma2(A.y, w2lo, aA1c0);                                \
            aB0c0 = ffma2(B.x, w2lo, aB0c0);                                \
            aB1c0 = ffma2(B.y, w2lo, aB1c0);                                \
            aA0c1 = ffma2(A.x, w2hi, aA0c1);                                \
            aA1c1 = ffma2(A.y, w2hi, aA1c1);                                \
            aB0c1 = ffma2(B.x, w2hi, aB0c1);                                \
            aB1c1 = ffma2(B.y, w2hi, aB1c1);                                \
        }                                                                   \
    }

    ull wA[4], wB[4];
    LOADW(wA, 0);
    for (int b = 0; b < 52; b += 2) {
        LOADW(wB, b + 1);
        COMPUTE(b, wA);
        if (b + 2 < 52) LOADW(wA, b + 2);
        COMPUTE(b + 1, wB);
    }
#undef LOADW
#undef COMPUTE

    // ---- epilogue: slotA rows = base+sel+{0..3}, slotB rows = base+4-sel+{0..3}
    {
        const int rA = n0 + base + sel;
        const int rB = n0 + base + 4 - sel;
        float x0, x1, y0, y1;
        // slot A, pair 0 (rows rA, rA+1)
        unpk(aA0c0, x0, x1); unpk(aA0c1, y0, y1);
        *(float2*)&g_part[ks][rA][c0]     = make_float2(x0, y0);
        *(float2*)&g_part[ks][rA + 1][c0] = make_float2(x1, y1);
        // slot A, pair 1 (rows rA+2, rA+3)
        unpk(aA1c0, x0, x1); unpk(aA1c1, y0, y1);
        *(float2*)&g_part[ks][rA + 2][c0] = make_float2(x0, y0);
        *(float2*)&g_part[ks][rA + 3][c0] = make_float2(x1, y1);
        // slot B, pair 0 (rows rB, rB+1)
        unpk(aB0c0, x0, x1); unpk(aB0c1, y0, y1);
        *(float2*)&g_part[ks][rB][c0]     = make_float2(x0, y0);
        *(float2*)&g_part[ks][rB + 1][c0] = make_float2(x1, y1);
        // slot B, pair 1 (rows rB+2, rB+3)
        unpk(aB1c0, x0, x1); unpk(aB1c1, y0, y1);
        *(float2*)&g_part[ks][rB + 2][c0] = make_float2(x0, y0);
        *(float2*)&g_part[ks][rB + 3][c0] = make_float2(x1, y1);
    }
}

// ---------------------------------------------------------------------------
// K3b: reduce 8 partials -> mix+leaky -> GRU. grid 128 x 512 threads.
// ---------------------------------------------------------------------------
__global__ void __launch_bounds__(512) k3b_tail(
        const float* __restrict__ postb,
        const float* __restrict__ mixW, const float* __restrict__ mixb,
        const float* __restrict__ hidden, float* __restrict__ out) {
    __shared__ float YsT[128 * 20];
    __shared__ float XsT[128 * 20];
    __shared__ float HsT[128 * 20];
    const int tid = threadIdx.x;
    const int n0 = blockIdx.x * 16;

    // reduce post partials + stage hidden (both transposed)
#pragma unroll
    for (int j = 0; j < 4; j++) {
        int idx = tid + j * 512;
        int r = idx >> 7, c = idx & 127;
        HsT[c * 20 + r] = hidden[(size_t)(n0 + r) * 128 + c];
        float v = postb[c];
#pragma unroll
        for (int p = 0; p < 8; p++) v += g_part[p][n0 + r][c];
        YsT[c * 20 + r] = v;
    }
    __syncthreads();

    const int w = tid >> 5, lane = tid & 31;
    const int rg = lane >> 2;          // rows rg*2, rg*2+1
    const int cp = lane & 3;
    const int c0 = w * 8 + cp * 2;

    // ---- mix + leaky ----
    {
        ull m0 = 0, m1 = 0;
        const float* wp = mixW + c0;
#pragma unroll 8
        for (int k = 0; k < 128; k++) {
            float2 yv = *(const float2*)&YsT[k * 20 + rg * 2];
            ull wv = *(const ull*)(wp + k * 128);
            m0 = ffma2(dup(yv.x), wv, m0);
            m1 = ffma2(dup(yv.y), wv, m1);
        }
        float b0 = mixb[c0], b1 = mixb[c0 + 1];
        float x0, x1, x2, x3;
        unpk(m0, x0, x1); unpk(m1, x2, x3);
        x0 += b0; x1 += b1; x2 += b0; x3 += b1;
        x0 = (x0 > 0.f) ? x0 : 0.01f * x0;
        x1 = (x1 > 0.f) ? x1 : 0.01f * x1;
        x2 = (x2 > 0.f) ? x2 : 0.01f * x2;
        x3 = (x3 > 0.f) ? x3 : 0.01f * x3;
        *(float2*)&XsT[c0 * 20 + rg * 2]       = make_float2(x0, x2);
        *(float2*)&XsT[(c0 + 1) * 20 + rg * 2] = make_float2(x1, x3);
    }
    __syncthreads();

    // ---- GRU ----
    ull R0 = 0, R1 = 0, Z0 = 0, Z1 = 0, I0 = 0, I1 = 0, N0 = 0, N1 = 0;
    const float* wi = g_WihT + c0;
    const float* wh = g_WhhT + c0;
#pragma unroll 4
    for (int k = 0; k < 128; k++) {
        float2 xv = *(const float2*)&XsT[k * 20 + rg * 2];
        float2 hv = *(const float2*)&HsT[k * 20 + rg * 2];
        const float* wik = wi + k * 384;
        const float* whk = wh + k * 384;
        ull wr = *(const ull*)(wik);
        ull wz = *(const ull*)(wik + 128);
        ull wn = *(const ull*)(wik + 256);
        ull vr = *(const ull*)(whk);
        ull vz = *(const ull*)(whk + 128);
        ull vn = *(const ull*)(whk + 256);
        ull dx0 = dup(xv.x), dx1 = dup(xv.y);
        ull dh0 = dup(hv.x), dh1 = dup(hv.y);
        R0 = ffma2(dx0, wr, R0); R0 = ffma2(dh0, vr, R0);
        R1 = ffma2(dx1, wr, R1); R1 = ffma2(dh1, vr, R1);
        Z0 = ffma2(dx0, wz, Z0); Z0 = ffma2(dh0, vz, Z0);
        Z1 = ffma2(dx1, wz, Z1); Z1 = ffma2(dh1, vz, Z1);
        I0 = ffma2(dx0, wn, I0);
        I1 = ffma2(dx1, wn, I1);
        N0 = ffma2(dh0, vn, N0);
        N1 = ffma2(dh1, vn, N1);
    }

    // epilogue: lane owns rows {rg*2, rg*2+1} x cols {c0, c0+1}
    {
        float Ra, Rb, Rc, Rd, Za, Zb, Zc, Zd;
        float Ia, Ib, Ic, Id, Na, Nb, Nc, Nd;
        unpk(R0, Ra, Rb); unpk(R1, Rc, Rd);
        unpk(Z0, Za, Zb); unpk(Z1, Zc, Zd);
        unpk(I0, Ia, Ib); unpk(I1, Ic, Id);
        unpk(N0, Na, Nb); unpk(N1, Nc, Nd);
        float h_a = HsT[c0 * 20 + rg * 2];
        float h_c = HsT[c0 * 20 + rg * 2 + 1];
        float h_b = HsT[(c0 + 1) * 20 + rg * 2];
        float h_d = HsT[(c0 + 1) * 20 + rg * 2 + 1];

        float rv, zv, nv;
        rv = 1.f / (1.f + expf(-Ra)); zv = 1.f / (1.f + expf(-Za));
        nv = tanhf(Ia + rv * Na);
        float oa = (1.f - zv) * nv + zv * h_a;
        rv = 1.f / (1.f + expf(-Rb)); zv = 1.f / (1.f + expf(-Zb));
        nv = tanhf(Ib + rv * Nb);
        float ob = (1.f - zv) * nv + zv * h_b;
        rv = 1.f / (1.f + expf(-Rc)); zv = 1.f / (1.f + expf(-Zc));
        nv = tanhf(Ic + rv * Nc);
        float oc = (1.f - zv) * nv + zv * h_c;
        rv = 1.f / (1.f + expf(-Rd)); zv = 1.f / (1.f + expf(-Zd));
        nv = tanhf(Id + rv * Nd);
        float od = (1.f - zv) * nv + zv * h_d;

        *(float2*)&out[(size_t)(n0 + rg * 2) * 128 + c0]     = make_float2(oa, ob);
        *(float2*)&out[(size_t)(n0 + rg * 2 + 1) * 128 + c0] = make_float2(oc, od);
    }
}

// ---------------------------------------------------------------------------
extern "C" void kernel_launch(void* const* d_in, const int* in_sizes, int n_in,
                              void* d_out, int out_size) {
    const float* input  = (const float*)d_in[0];
    const float* adj    = (const float*)d_in[1];
    const float* adjf   = (const float*)d_in[2];
    const float* hidden = (const float*)d_in[3];
    const float* preW   = (const float*)d_in[4];
    const float* preb   = (const float*)d_in[5];
    const float* postW  = (const float*)d_in[6];
    const float* postb  = (const float*)d_in[7];
    const float* mixW   = (const float*)d_in[8];
    const float* mixb   = (const float*)d_in[9];
    const float* Wih    = (const float*)d_in[10];
    const float* Whh    = (const float*)d_in[11];
    float* out = (float*)d_out;

    cudaFuncSetAttribute(k3a_post, cudaFuncAttributeMaxDynamicSharedMemorySize, SMEM_K3A);

    k0_prep<<<384, 128>>>(Wih, Whh);
    k1_hij<<<256, 128>>>(input, preW);
    k2_agg<<<BN, 128>>>(adj, adjf, preW, preb);
    k3a_post<<<256, 512, SMEM_K3A>>>(postW);
    k3b_tail<<<128, 512>>>(postb, mixW, mixb, hidden, out);
}

// round 8
// speedup vs baseline: 1.8345x; 1.0795x over previous
#include <cuda_runtime.h>
#include <math.h>

#define BN 2048
#define NN 256
#define MD 1664

typedef unsigned long long ull;

__device__ float g_hi[BN * 128];
__device__ float g_hj[BN * 128];
__device__ float g_m[(size_t)BN * MD];
__device__ float g_part[8][BN][128];
__device__ float g_WihT[128 * 384];
__device__ float g_WhhT[128 * 384];

__device__ __forceinline__ ull ffma2(ull a, ull b, ull c) {
    ull d;
    asm("fma.rn.f32x2 %0, %1, %2, %3;" : "=l"(d) : "l"(a), "l"(b), "l"(c));
    return d;
}
__device__ __forceinline__ ull dup(float a) {
    ull d; asm("mov.b64 %0, {%1,%1};" : "=l"(d) : "f"(a)); return d;
}
__device__ __forceinline__ void unpk(ull v, float& x, float& y) {
    asm("mov.b64 {%0,%1}, %2;" : "=f"(x), "=f"(y) : "l"(v));
}

// ---------------------------------------------------------------------------
// K1: hi/hj projections + input -> g_m[:,0:128] + GRU weight transpose
// 256 blocks x 128 threads, 8 rows/block
// ---------------------------------------------------------------------------
__global__ void __launch_bounds__(128) k1_hij(const float* __restrict__ input,
                                              const float* __restrict__ preW,
                                              const float* __restrict__ Wih,
                                              const float* __restrict__ Whh) {
    __shared__ float As[8 * 128];
    int t = threadIdx.x;
    int n0 = blockIdx.x * 8;

    // GRU transpose: grid-stride over all 384*128 elements
    for (int idx = blockIdx.x * 128 + t; idx < 384 * 128; idx += 256 * 128) {
        int r = idx >> 7, c = idx & 127;
        g_WihT[c * 384 + r] = Wih[idx];
        g_WhhT[c * 384 + r] = Whh[idx];
    }

    for (int s = t; s < 8 * 128; s += 128) {
        float v = input[(size_t)n0 * 128 + s];
        As[s] = v;
        g_m[(size_t)(n0 + (s >> 7)) * MD + (s & 127)] = v;
    }
    __syncthreads();

    float hi[8], hj[8];
#pragma unroll
    for (int r = 0; r < 8; r++) { hi[r] = 0.f; hj[r] = 0.f; }

    for (int e = 0; e < 128; e += 4) {
        float wi0 = preW[(e + 0) * 128 + t];
        float wi1 = preW[(e + 1) * 128 + t];
        float wi2 = preW[(e + 2) * 128 + t];
        float wi3 = preW[(e + 3) * 128 + t];
        float wj0 = preW[(128 + e + 0) * 128 + t];
        float wj1 = preW[(128 + e + 1) * 128 + t];
        float wj2 = preW[(128 + e + 2) * 128 + t];
        float wj3 = preW[(128 + e + 3) * 128 + t];
#pragma unroll
        for (int r = 0; r < 8; r++) {
            const float4 a = *(const float4*)&As[r * 128 + e];
            hi[r] += a.x * wi0 + a.y * wi1 + a.z * wi2 + a.w * wi3;
            hj[r] += a.x * wj0 + a.y * wj1 + a.z * wj2 + a.w * wj3;
        }
    }
#pragma unroll
    for (int r = 0; r < 8; r++) {
        g_hi[(size_t)(n0 + r) * 128 + t] = hi[r];
        g_hj[(size_t)(n0 + r) * 128 + t] = hj[r];
    }
}

// ---------------------------------------------------------------------------
// K2 v2: per-node aggregation. 32-edge batches, f32x2 edge-pair packing.
// EST=36 floats (144B) keeps all 16B vector loads aligned.
// ---------------------------------------------------------------------------
#define EST 36

__global__ void __launch_bounds__(128) k2_agg(const float* __restrict__ adj,
                                              const float* __restrict__ adjf,
                                              const float* __restrict__ preW,
                                              const float* __restrict__ preb) {
    __shared__ float WeS[64 * 128];      // [de][c]
    __shared__ float efT[64 * EST];      // [de][32 edges]
    __shared__ int   nbr[NN];
    __shared__ int   cnt;

    const int t = threadIdx.x;
    const int node = blockIdx.x;
    const int nbase = (node >> 8) << 8;

    // stage We (rows 256..319 of preW)
    {
        const float4* src = (const float4*)(preW + 256 * 128);
        float4* dst = (float4*)WeS;
#pragma unroll
        for (int i = 0; i < 16; i++) dst[t + i * 128] = src[t + i * 128];
    }
    if (t == 0) cnt = 0;
    __syncthreads();

    const float* arow = adj + (size_t)node * NN;
    for (int j = t; j < NN; j += 128)
        if (arow[j] > 0.0f) { int p = atomicAdd(&cnt, 1); nbr[p] = j; }
    __syncthreads();

    const int deg = cnt;
    const float base = g_hi[(size_t)node * 128 + t] + preb[t];
    float s1 = 0.f, s2 = 0.f, mx = -1e30f, mn = 1e30f;
    const float* efb = adjf + (size_t)node * NN * 64;

    for (int p0 = 0; p0 < deg; p0 += 32) {
        __syncthreads();   // protect efT vs previous batch readers
        // stage 32 edges x 64 de, transposed. thread: e=t&31, kc=(t>>5)*16
        {
            const int e = t & 31, kc = (t >> 5) * 16;
            const int j = (p0 + e < deg) ? nbr[p0 + e] : -1;
            if (j >= 0) {
                const float* src = efb + (size_t)j * 64 + kc;
#pragma unroll
                for (int i = 0; i < 16; i += 4) {
                    float4 v = *(const float4*)(src + i);
                    efT[(kc + i + 0) * EST + e] = v.x;
                    efT[(kc + i + 1) * EST + e] = v.y;
                    efT[(kc + i + 2) * EST + e] = v.z;
                    efT[(kc + i + 3) * EST + e] = v.w;
                }
            } else {
#pragma unroll
                for (int i = 0; i < 16; i++) efT[(kc + i) * EST + e] = 0.f;
            }
        }
        __syncthreads();

        ull acc[16];
#pragma unroll
        for (int p = 0; p < 16; p++) acc[p] = 0;

#pragma unroll 4
        for (int de = 0; de < 64; de++) {
            ull w2 = dup(WeS[de * 128 + t]);
            const ull* efr = (const ull*)&efT[de * EST];
#pragma unroll
            for (int q = 0; q < 8; q++) {
                ulonglong2 e2 = *(const ulonglong2*)&efr[q * 2];
                acc[q * 2]     = ffma2(e2.x, w2, acc[q * 2]);
                acc[q * 2 + 1] = ffma2(e2.y, w2, acc[q * 2 + 1]);
            }
        }

#pragma unroll
        for (int p = 0; p < 16; p++) {
            float ea, eb;
            unpk(acc[p], ea, eb);
            int i0 = p0 + 2 * p, i1 = i0 + 1;
            if (i0 < deg) {
                float hj = g_hj[(size_t)(nbase + nbr[i0]) * 128 + t];
                float tv = base + hj + ea;
                s1 += tv; s2 += tv * tv;
                mx = fmaxf(mx, tv); mn = fminf(mn, tv);
            }
            if (i1 < deg) {
                float hj = g_hj[(size_t)(nbase + nbr[i1]) * 128 + t];
                float tv = base + hj + eb;
                s1 += tv; s2 += tv * tv;
                mx = fmaxf(mx, tv); mn = fminf(mn, tv);
            }
        }
    }

    float degf = (float)deg;
    float degc = fmaxf(degf, 1e-5f);
    float mean = s1 / degc;
    float var = s2 / degc - mean * mean;
    if (var < 0.f) var = 0.f;
    float sd = sqrtf(var + 1e-5f);
    float mxo = (deg > 0) ? mx : 0.f;
    float mno = (deg > 0) ? mn : 0.f;
    float slog = logf(degf + 1.0f) / 3.3f;
    float inv = 1.0f / (slog + 1e-5f);

    float* mrow = g_m + (size_t)node * MD;
    mrow[ 128 + t] = mean;        mrow[ 256 + t] = mxo;
    mrow[ 384 + t] = mno;         mrow[ 512 + t] = sd;
    mrow[ 640 + t] = mean * slog; mrow[ 768 + t] = mxo * slog;
    mrow[ 896 + t] = mno * slog;  mrow[1024 + t] = sd * slog;
    mrow[1152 + t] = mean * inv;  mrow[1280 + t] = mxo * inv;
    mrow[1408 + t] = mno * inv;   mrow[1536 + t] = sd * inv;
}

// ---------------------------------------------------------------------------
// K3a v3: 256 blocks (32 rowblocks x 8 ksplits), 256 threads (8 warps).
// Warp = 64 rows x 16 cols; lane = 8 rows (staggered pairs) x 4 cols.
// ---------------------------------------------------------------------------
#define KSP 208
#define AST 68
#define SMEM_K3A (KSP * AST * 4)   // 56576 B

__global__ void __launch_bounds__(256, 2) k3a_post(const float* __restrict__ postW) {
    extern __shared__ float AsT[];   // [KSP][AST]
    const int tid = threadIdx.x;
    const int w = tid >> 5, lane = tid & 31;
    const int rb = blockIdx.x & 31, ks = blockIdx.x >> 5;
    const int n0 = rb * 64, k0 = ks * KSP;

    // stage A transposed: thread r = tid>>2 (0..63), kt = (tid&3)*52
    {
        const int r = tid >> 2;
        const int kt = (tid & 3) * 52;
        const float* src = g_m + (size_t)(n0 + r) * MD + k0 + kt;
#pragma unroll
        for (int i = 0; i < 52; i += 4) {
            float4 v = *(const float4*)(src + i);
            AsT[(kt + i + 0) * AST + r] = v.x;
            AsT[(kt + i + 1) * AST + r] = v.y;
            AsT[(kt + i + 2) * AST + r] = v.z;
            AsT[(kt + i + 3) * AST + r] = v.w;
        }
    }
    __syncthreads();

    const int rg = lane >> 2;
    const int cp = lane & 3;
    const int c0 = w * 16 + cp * 4;
    const int bs = rg * 8;
    const int sel = (rg >= 4) ? 4 : 0;
    const int offA = bs + sel;
    const int offB = bs + 4 - sel;

    const float* wp = postW + (size_t)k0 * 128 + c0;

    ull aA0[4], aA1[4], aB0[4], aB1[4];
#pragma unroll
    for (int c = 0; c < 4; c++) { aA0[c] = 0; aA1[c] = 0; aB0[c] = 0; aB1[c] = 0; }

#define LOADW(buf, b)                                                       \
    {                                                                       \
        _Pragma("unroll")                                                   \
        for (int j = 0; j < 4; j++)                                         \
            buf[j] = *(const float4*)(wp + (size_t)((b) * 4 + j) * 128);    \
    }
#define COMPUTE(b, buf)                                                     \
    {                                                                       \
        _Pragma("unroll")                                                   \
        for (int j = 0; j < 4; j++) {                                       \
            const int k = (b) * 4 + j;                                      \
            ulonglong2 A = *(const ulonglong2*)&AsT[k * AST + offA];        \
            ulonglong2 B = *(const ulonglong2*)&AsT[k * AST + offB];        \
            ull w0 = dup(buf[j].x), w1 = dup(buf[j].y);                     \
            ull w2 = dup(buf[j].z), w3 = dup(buf[j].w);                     \
            aA0[0] = ffma2(A.x, w0, aA0[0]); aA0[1] = ffma2(A.x, w1, aA0[1]); \
            aA0[2] = ffma2(A.x, w2, aA0[2]); aA0[3] = ffma2(A.x, w3, aA0[3]); \
            aA1[0] = ffma2(A.y, w0, aA1[0]); aA1[1] = ffma2(A.y, w1, aA1[1]); \
            aA1[2] = ffma2(A.y, w2, aA1[2]); aA1[3] = ffma2(A.y, w3, aA1[3]); \
            aB0[0] = ffma2(B.x, w0, aB0[0]); aB0[1] = ffma2(B.x, w1, aB0[1]); \
            aB0[2] = ffma2(B.x, w2, aB0[2]); aB0[3] = ffma2(B.x, w3, aB0[3]); \
            aB1[0] = ffma2(B.y, w0, aB1[0]); aB1[1] = ffma2(B.y, w1, aB1[1]); \
            aB1[2] = ffma2(B.y, w2, aB1[2]); aB1[3] = ffma2(B.y, w3, aB1[3]); \
        }                                                                   \
    }

    float4 wA[4], wB[4];
    LOADW(wA, 0);
    for (int b = 0; b < 52; b += 2) {
        LOADW(wB, b + 1);
        COMPUTE(b, wA);
        if (b + 2 < 52) LOADW(wA, b + 2);
        COMPUTE(b + 1, wB);
    }
#undef LOADW
#undef COMPUTE

    // epilogue: 8 rows x 4 cols per lane
    {
        const int rA = n0 + offA;
        const int rB = n0 + offB;
        float lo[4], hi[4];
#pragma unroll
        for (int c = 0; c < 4; c++) unpk(aA0[c], lo[c], hi[c]);
        *(float4*)&g_part[ks][rA][c0]     = make_float4(lo[0], lo[1], lo[2], lo[3]);
        *(float4*)&g_part[ks][rA + 1][c0] = make_float4(hi[0], hi[1], hi[2], hi[3]);
#pragma unroll
        for (int c = 0; c < 4; c++) unpk(aA1[c], lo[c], hi[c]);
        *(float4*)&g_part[ks][rA + 2][c0] = make_float4(lo[0], lo[1], lo[2], lo[3]);
        *(float4*)&g_part[ks][rA + 3][c0] = make_float4(hi[0], hi[1], hi[2], hi[3]);
#pragma unroll
        for (int c = 0; c < 4; c++) unpk(aB0[c], lo[c], hi[c]);
        *(float4*)&g_part[ks][rB][c0]     = make_float4(lo[0], lo[1], lo[2], lo[3]);
        *(float4*)&g_part[ks][rB + 1][c0] = make_float4(hi[0], hi[1], hi[2], hi[3]);
#pragma unroll
        for (int c = 0; c < 4; c++) unpk(aB1[c], lo[c], hi[c]);
        *(float4*)&g_part[ks][rB + 2][c0] = make_float4(lo[0], lo[1], lo[2], lo[3]);
        *(float4*)&g_part[ks][rB + 3][c0] = make_float4(hi[0], hi[1], hi[2], hi[3]);
    }
}

// ---------------------------------------------------------------------------
// K3b: reduce partials -> mix+leaky -> GRU. grid 128 x 512 threads.
// ---------------------------------------------------------------------------
__global__ void __launch_bounds__(512) k3b_tail(
        const float* __restrict__ postb,
        const float* __restrict__ mixW, const float* __restrict__ mixb,
        const float* __restrict__ hidden, float* __restrict__ out) {
    __shared__ float YsT[128 * 20];
    __shared__ float XsT[128 * 20];
    __shared__ float HsT[128 * 20];
    const int tid = threadIdx.x;
    const int n0 = blockIdx.x * 16;

#pragma unroll
    for (int j = 0; j < 4; j++) {
        int idx = tid + j * 512;
        int r = idx >> 7, c = idx & 127;
        HsT[c * 20 + r] = hidden[(size_t)(n0 + r) * 128 + c];
        float v = postb[c];
#pragma unroll
        for (int p = 0; p < 8; p++) v += g_part[p][n0 + r][c];
        YsT[c * 20 + r] = v;
    }
    __syncthreads();

    const int w = tid >> 5, lane = tid & 31;
    const int rg = lane >> 2;
    const int cp = lane & 3;
    const int c0 = w * 8 + cp * 2;

    // ---- mix + leaky ----
    {
        ull m0 = 0, m1 = 0;
        const float* wpm = mixW + c0;
#pragma unroll 8
        for (int k = 0; k < 128; k++) {
            float2 yv = *(const float2*)&YsT[k * 20 + rg * 2];
            ull wv = *(const ull*)(wpm + k * 128);
            m0 = ffma2(dup(yv.x), wv, m0);
            m1 = ffma2(dup(yv.y), wv, m1);
        }
        float b0 = mixb[c0], b1 = mixb[c0 + 1];
        float x0, x1, x2, x3;
        unpk(m0, x0, x1); unpk(m1, x2, x3);
        x0 += b0; x1 += b1; x2 += b0; x3 += b1;
        x0 = (x0 > 0.f) ? x0 : 0.01f * x0;
        x1 = (x1 > 0.f) ? x1 : 0.01f * x1;
        x2 = (x2 > 0.f) ? x2 : 0.01f * x2;
        x3 = (x3 > 0.f) ? x3 : 0.01f * x3;
        *(float2*)&XsT[c0 * 20 + rg * 2]       = make_float2(x0, x2);
        *(float2*)&XsT[(c0 + 1) * 20 + rg * 2] = make_float2(x1, x3);
    }
    __syncthreads();

    // ---- GRU ----
    ull R0 = 0, R1 = 0, Z0 = 0, Z1 = 0, I0 = 0, I1 = 0, N0 = 0, N1 = 0;
    const float* wi = g_WihT + c0;
    const float* wh = g_WhhT + c0;
#pragma unroll 4
    for (int k = 0; k < 128; k++) {
        float2 xv = *(const float2*)&XsT[k * 20 + rg * 2];
        float2 hv = *(const float2*)&HsT[k * 20 + rg * 2];
        const float* wik = wi + k * 384;
        const float* whk = wh + k * 384;
        ull wr = *(const ull*)(wik);
        ull wz = *(const ull*)(wik + 128);
        ull wn = *(const ull*)(wik + 256);
        ull vr = *(const ull*)(whk);
        ull vz = *(const ull*)(whk + 128);
        ull vn = *(const ull*)(whk + 256);
        ull dx0 = dup(xv.x), dx1 = dup(xv.y);
        ull dh0 = dup(hv.x), dh1 = dup(hv.y);
        R0 = ffma2(dx0, wr, R0); R0 = ffma2(dh0, vr, R0);
        R1 = ffma2(dx1, wr, R1); R1 = ffma2(dh1, vr, R1);
        Z0 = ffma2(dx0, wz, Z0); Z0 = ffma2(dh0, vz, Z0);
        Z1 = ffma2(dx1, wz, Z1); Z1 = ffma2(dh1, vz, Z1);
        I0 = ffma2(dx0, wn, I0);
        I1 = ffma2(dx1, wn, I1);
        N0 = ffma2(dh0, vn, N0);
        N1 = ffma2(dh1, vn, N1);
    }

    {
        float Ra, Rb, Rc, Rd, Za, Zb, Zc, Zd;
        float Ia, Ib, Ic, Id, Na, Nb, Nc, Nd;
        unpk(R0, Ra, Rb); unpk(R1, Rc, Rd);
        unpk(Z0, Za, Zb); unpk(Z1, Zc, Zd);
        unpk(I0, Ia, Ib); unpk(I1, Ic, Id);
        unpk(N0, Na, Nb); unpk(N1, Nc, Nd);
        float h_a = HsT[c0 * 20 + rg * 2];
        float h_c = HsT[c0 * 20 + rg * 2 + 1];
        float h_b = HsT[(c0 + 1) * 20 + rg * 2];
        float h_d = HsT[(c0 + 1) * 20 + rg * 2 + 1];

        float rv, zv, nv;
        rv = 1.f / (1.f + expf(-Ra)); zv = 1.f / (1.f + expf(-Za));
        nv = tanhf(Ia + rv * Na);
        float oa = (1.f - zv) * nv + zv * h_a;
        rv = 1.f / (1.f + expf(-Rb)); zv = 1.f / (1.f + expf(-Zb));
        nv = tanhf(Ib + rv * Nb);
        float ob = (1.f - zv) * nv + zv * h_b;
        rv = 1.f / (1.f + expf(-Rc)); zv = 1.f / (1.f + expf(-Zc));
        nv = tanhf(Ic + rv * Nc);
        float oc = (1.f - zv) * nv + zv * h_c;
        rv = 1.f / (1.f + expf(-Rd)); zv = 1.f / (1.f + expf(-Zd));
        nv = tanhf(Id + rv * Nd);
        float od = (1.f - zv) * nv + zv * h_d;

        *(float2*)&out[(size_t)(n0 + rg * 2) * 128 + c0]     = make_float2(oa, ob);
        *(float2*)&out[(size_t)(n0 + rg * 2 + 1) * 128 + c0] = make_float2(oc, od);
    }
}

// ---------------------------------------------------------------------------
extern "C" void kernel_launch(void* const* d_in, const int* in_sizes, int n_in,
                              void* d_out, int out_size) {
    const float* input  = (const float*)d_in[0];
    const float* adj    = (const float*)d_in[1];
    const float* adjf   = (const float*)d_in[2];
    const float* hidden = (const float*)d_in[3];
    const float* preW   = (const float*)d_in[4];
    const float* preb   = (const float*)d_in[5];
    const float* postW  = (const float*)d_in[6];
    const float* postb  = (const float*)d_in[7];
    const float* mixW   = (const float*)d_in[8];
    const float* mixb   = (const float*)d_in[9];
    const float* Wih    = (const float*)d_in[10];
    const float* Whh    = (const float*)d_in[11];
    float* out = (float*)d_out;

    cudaFuncSetAttribute(k3a_post, cudaFuncAttributeMaxDynamicSharedMemorySize, SMEM_K3A);

    k1_hij<<<256, 128>>>(input, preW, Wih, Whh);
    k2_agg<<<BN, 128>>>(adj, adjf, preW, preb);
    k3a_post<<<256, 256, SMEM_K3A>>>(postW);
    k3b_tail<<<128, 512>>>(postb, mixW, mixb, hidden, out);
}

// round 9
// speedup vs baseline: 2.1549x; 1.1747x over previous
#include <cuda_runtime.h>
#include <math.h>

#define BN 2048
#define NN 256
#define MD 1664

typedef unsigned long long ull;

__device__ float g_hi[BN * 128];
__device__ float g_hj[BN * 128];
__device__ float g_m[(size_t)BN * MD];
__device__ float g_part[8][BN][128];
__device__ float g_WgT[256 * 384];     // [k][gatecol]; k<128 = X (Wih), k>=128 = H (Whh)
__device__ float g_x[BN * 128];        // mix output
__device__ float g_gate[(size_t)BN * 384];  // r_sum | z_sum | i_n
__device__ float g_gateH[BN * 128];    // h_n

__device__ __forceinline__ ull ffma2(ull a, ull b, ull c) {
    ull d;
    asm("fma.rn.f32x2 %0, %1, %2, %3;" : "=l"(d) : "l"(a), "l"(b), "l"(c));
    return d;
}
__device__ __forceinline__ ull dup(float a) {
    ull d; asm("mov.b64 %0, {%1,%1};" : "=l"(d) : "f"(a)); return d;
}
__device__ __forceinline__ void unpk(ull v, float& x, float& y) {
    asm("mov.b64 {%0,%1}, %2;" : "=f"(x), "=f"(y) : "l"(v));
}

// ---------------------------------------------------------------------------
// K1: hi/hj projections + input -> g_m[:,0:128] + combined GRU weight transpose
// ---------------------------------------------------------------------------
__global__ void __launch_bounds__(128) k1_hij(const float* __restrict__ input,
                                              const float* __restrict__ preW,
                                              const float* __restrict__ Wih,
                                              const float* __restrict__ Whh) {
    __shared__ float As[8 * 128];
    int t = threadIdx.x;
    int n0 = blockIdx.x * 8;

    // combined transposed GRU weights: WgT[c][r] = Wih[r][c], WgT[128+c][r] = Whh[r][c]
    for (int idx = blockIdx.x * 128 + t; idx < 384 * 128; idx += 256 * 128) {
        int r = idx >> 7, c = idx & 127;
        g_WgT[c * 384 + r]         = Wih[idx];
        g_WgT[(128 + c) * 384 + r] = Whh[idx];
    }

    for (int s = t; s < 8 * 128; s += 128) {
        float v = input[(size_t)n0 * 128 + s];
        As[s] = v;
        g_m[(size_t)(n0 + (s >> 7)) * MD + (s & 127)] = v;
    }
    __syncthreads();

    float hi[8], hj[8];
#pragma unroll
    for (int r = 0; r < 8; r++) { hi[r] = 0.f; hj[r] = 0.f; }

    for (int e = 0; e < 128; e += 4) {
        float wi0 = preW[(e + 0) * 128 + t];
        float wi1 = preW[(e + 1) * 128 + t];
        float wi2 = preW[(e + 2) * 128 + t];
        float wi3 = preW[(e + 3) * 128 + t];
        float wj0 = preW[(128 + e + 0) * 128 + t];
        float wj1 = preW[(128 + e + 1) * 128 + t];
        float wj2 = preW[(128 + e + 2) * 128 + t];
        float wj3 = preW[(128 + e + 3) * 128 + t];
#pragma unroll
        for (int r = 0; r < 8; r++) {
            const float4 a = *(const float4*)&As[r * 128 + e];
            hi[r] += a.x * wi0 + a.y * wi1 + a.z * wi2 + a.w * wi3;
            hj[r] += a.x * wj0 + a.y * wj1 + a.z * wj2 + a.w * wj3;
        }
    }
#pragma unroll
    for (int r = 0; r < 8; r++) {
        g_hi[(size_t)(n0 + r) * 128 + t] = hi[r];
        g_hj[(size_t)(n0 + r) * 128 + t] = hj[r];
    }
}

// ---------------------------------------------------------------------------
// K2: per-node aggregation. 32-edge batches, f32x2 edge-pair packing. EST=36.
// ---------------------------------------------------------------------------
#define EST 36

__global__ void __launch_bounds__(128) k2_agg(const float* __restrict__ adj,
                                              const float* __restrict__ adjf,
                                              const float* __restrict__ preW,
                                              const float* __restrict__ preb) {
    __shared__ float WeS[64 * 128];
    __shared__ float efT[64 * EST];
    __shared__ int   nbr[NN];
    __shared__ int   cnt;

    const int t = threadIdx.x;
    const int node = blockIdx.x;
    const int nbase = (node >> 8) << 8;

    {
        const float4* src = (const float4*)(preW + 256 * 128);
        float4* dst = (float4*)WeS;
#pragma unroll
        for (int i = 0; i < 16; i++) dst[t + i * 128] = src[t + i * 128];
    }
    if (t == 0) cnt = 0;
    __syncthreads();

    const float* arow = adj + (size_t)node * NN;
    for (int j = t; j < NN; j += 128)
        if (arow[j] > 0.0f) { int p = atomicAdd(&cnt, 1); nbr[p] = j; }
    __syncthreads();

    const int deg = cnt;
    const float base = g_hi[(size_t)node * 128 + t] + preb[t];
    float s1 = 0.f, s2 = 0.f, mx = -1e30f, mn = 1e30f;
    const float* efb = adjf + (size_t)node * NN * 64;

    for (int p0 = 0; p0 < deg; p0 += 32) {
        __syncthreads();
        {
            const int e = t & 31, kc = (t >> 5) * 16;
            const int j = (p0 + e < deg) ? nbr[p0 + e] : -1;
            if (j >= 0) {
                const float* src = efb + (size_t)j * 64 + kc;
#pragma unroll
                for (int i = 0; i < 16; i += 4) {
                    float4 v = *(const float4*)(src + i);
                    efT[(kc + i + 0) * EST + e] = v.x;
                    efT[(kc + i + 1) * EST + e] = v.y;
                    efT[(kc + i + 2) * EST + e] = v.z;
                    efT[(kc + i + 3) * EST + e] = v.w;
                }
            } else {
#pragma unroll
                for (int i = 0; i < 16; i++) efT[(kc + i) * EST + e] = 0.f;
            }
        }
        __syncthreads();

        ull acc[16];
#pragma unroll
        for (int p = 0; p < 16; p++) acc[p] = 0;

#pragma unroll 4
        for (int de = 0; de < 64; de++) {
            ull w2 = dup(WeS[de * 128 + t]);
            const ull* efr = (const ull*)&efT[de * EST];
#pragma unroll
            for (int q = 0; q < 8; q++) {
                ulonglong2 e2 = *(const ulonglong2*)&efr[q * 2];
                acc[q * 2]     = ffma2(e2.x, w2, acc[q * 2]);
                acc[q * 2 + 1] = ffma2(e2.y, w2, acc[q * 2 + 1]);
            }
        }

#pragma unroll
        for (int p = 0; p < 16; p++) {
            float ea, eb;
            unpk(acc[p], ea, eb);
            int i0 = p0 + 2 * p, i1 = i0 + 1;
            if (i0 < deg) {
                float hj = g_hj[(size_t)(nbase + nbr[i0]) * 128 + t];
                float tv = base + hj + ea;
                s1 += tv; s2 += tv * tv;
                mx = fmaxf(mx, tv); mn = fminf(mn, tv);
            }
            if (i1 < deg) {
                float hj = g_hj[(size_t)(nbase + nbr[i1]) * 128 + t];
                float tv = base + hj + eb;
                s1 += tv; s2 += tv * tv;
                mx = fmaxf(mx, tv); mn = fminf(mn, tv);
            }
        }
    }

    float degf = (float)deg;
    float degc = fmaxf(degf, 1e-5f);
    float mean = s1 / degc;
    float var = s2 / degc - mean * mean;
    if (var < 0.f) var = 0.f;
    float sd = sqrtf(var + 1e-5f);
    float mxo = (deg > 0) ? mx : 0.f;
    float mno = (deg > 0) ? mn : 0.f;
    float slog = logf(degf + 1.0f) / 3.3f;
    float inv = 1.0f / (slog + 1e-5f);

    float* mrow = g_m + (size_t)node * MD;
    mrow[ 128 + t] = mean;        mrow[ 256 + t] = mxo;
    mrow[ 384 + t] = mno;         mrow[ 512 + t] = sd;
    mrow[ 640 + t] = mean * slog; mrow[ 768 + t] = mxo * slog;
    mrow[ 896 + t] = mno * slog;  mrow[1024 + t] = sd * slog;
    mrow[1152 + t] = mean * inv;  mrow[1280 + t] = mxo * inv;
    mrow[1408 + t] = mno * inv;   mrow[1536 + t] = sd * inv;
}

// ---------------------------------------------------------------------------
// K3a: post-GEMM partials. (unchanged from R8)
// ---------------------------------------------------------------------------
#define KSP 208
#define AST 68
#define SMEM_K3A (KSP * AST * 4)

__global__ void __launch_bounds__(256, 2) k3a_post(const float* __restrict__ postW) {
    extern __shared__ float AsT[];
    const int tid = threadIdx.x;
    const int w = tid >> 5, lane = tid & 31;
    const int rb = blockIdx.x & 31, ks = blockIdx.x >> 5;
    const int n0 = rb * 64, k0 = ks * KSP;

    {
        const int r = tid >> 2;
        const int kt = (tid & 3) * 52;
        const float* src = g_m + (size_t)(n0 + r) * MD + k0 + kt;
#pragma unroll
        for (int i = 0; i < 52; i += 4) {
            float4 v = *(const float4*)(src + i);
            AsT[(kt + i + 0) * AST + r] = v.x;
            AsT[(kt + i + 1) * AST + r] = v.y;
            AsT[(kt + i + 2) * AST + r] = v.z;
            AsT[(kt + i + 3) * AST + r] = v.w;
        }
    }
    __syncthreads();

    const int rg = lane >> 2;
    const int cp = lane & 3;
    const int c0 = w * 16 + cp * 4;
    const int bs = rg * 8;
    const int sel = (rg >= 4) ? 4 : 0;
    const int offA = bs + sel;
    const int offB = bs + 4 - sel;

    const float* wp = postW + (size_t)k0 * 128 + c0;

    ull aA0[4], aA1[4], aB0[4], aB1[4];
#pragma unroll
    for (int c = 0; c < 4; c++) { aA0[c] = 0; aA1[c] = 0; aB0[c] = 0; aB1[c] = 0; }

#define LOADW3(buf, b)                                                      \
    {                                                                       \
        _Pragma("unroll")                                                   \
        for (int j = 0; j < 4; j++)                                         \
            buf[j] = *(const float4*)(wp + (size_t)((b) * 4 + j) * 128);    \
    }
#define COMP3(b, buf)                                                       \
    {                                                                       \
        _Pragma("unroll")                                                   \
        for (int j = 0; j < 4; j++) {                                       \
            const int k = (b) * 4 + j;                                      \
            ulonglong2 A = *(const ulonglong2*)&AsT[k * AST + offA];        \
            ulonglong2 B = *(const ulonglong2*)&AsT[k * AST + offB];        \
            ull w0 = dup(buf[j].x), w1 = dup(buf[j].y);                     \
            ull w2 = dup(buf[j].z), w3 = dup(buf[j].w);                     \
            aA0[0] = ffma2(A.x, w0, aA0[0]); aA0[1] = ffma2(A.x, w1, aA0[1]); \
            aA0[2] = ffma2(A.x, w2, aA0[2]); aA0[3] = ffma2(A.x, w3, aA0[3]); \
            aA1[0] = ffma2(A.y, w0, aA1[0]); aA1[1] = ffma2(A.y, w1, aA1[1]); \
            aA1[2] = ffma2(A.y, w2, aA1[2]); aA1[3] = ffma2(A.y, w3, aA1[3]); \
            aB0[0] = ffma2(B.x, w0, aB0[0]); aB0[1] = ffma2(B.x, w1, aB0[1]); \
            aB0[2] = ffma2(B.x, w2, aB0[2]); aB0[3] = ffma2(B.x, w3, aB0[3]); \
            aB1[0] = ffma2(B.y, w0, aB1[0]); aB1[1] = ffma2(B.y, w1, aB1[1]); \
            aB1[2] = ffma2(B.y, w2, aB1[2]); aB1[3] = ffma2(B.y, w3, aB1[3]); \
        }                                                                   \
    }

    float4 wA[4], wB[4];
    LOADW3(wA, 0);
    for (int b = 0; b < 52; b += 2) {
        LOADW3(wB, b + 1);
        COMP3(b, wA);
        if (b + 2 < 52) LOADW3(wA, b + 2);
        COMP3(b + 1, wB);
    }
#undef LOADW3
#undef COMP3

    {
        const int rA = n0 + offA;
        const int rB = n0 + offB;
        float lo[4], hi[4];
#pragma unroll
        for (int c = 0; c < 4; c++) unpk(aA0[c], lo[c], hi[c]);
        *(float4*)&g_part[ks][rA][c0]     = make_float4(lo[0], lo[1], lo[2], lo[3]);
        *(float4*)&g_part[ks][rA + 1][c0] = make_float4(hi[0], hi[1], hi[2], hi[3]);
#pragma unroll
        for (int c = 0; c < 4; c++) unpk(aA1[c], lo[c], hi[c]);
        *(float4*)&g_part[ks][rA + 2][c0] = make_float4(lo[0], lo[1], lo[2], lo[3]);
        *(float4*)&g_part[ks][rA + 3][c0] = make_float4(hi[0], hi[1], hi[2], hi[3]);
#pragma unroll
        for (int c = 0; c < 4; c++) unpk(aB0[c], lo[c], hi[c]);
        *(float4*)&g_part[ks][rB][c0]     = make_float4(lo[0], lo[1], lo[2], lo[3]);
        *(float4*)&g_part[ks][rB + 1][c0] = make_float4(hi[0], hi[1], hi[2], hi[3]);
#pragma unroll
        for (int c = 0; c < 4; c++) unpk(aB1[c], lo[c], hi[c]);
        *(float4*)&g_part[ks][rB + 2][c0] = make_float4(lo[0], lo[1], lo[2], lo[3]);
        *(float4*)&g_part[ks][rB + 3][c0] = make_float4(hi[0], hi[1], hi[2], hi[3]);
    }
}

// ---------------------------------------------------------------------------
// K4: reduce partials + postb -> y1 tile; mix GEMM + leaky -> g_x.
// grid 128 (16 rows), 256 threads. Warp = 16 rows x 16 cols; lane = row-pair x 4 cols.
// ---------------------------------------------------------------------------
__global__ void __launch_bounds__(256) k4_mix(const float* __restrict__ postb,
                                              const float* __restrict__ mixW,
                                              const float* __restrict__ mixb) {
    __shared__ float YsT[128 * 20];
    const int tid = threadIdx.x;
    const int n0 = blockIdx.x * 16;

#pragma unroll
    for (int j = 0; j < 8; j++) {
        int idx = tid + j * 256;
        int r = idx >> 7, c = idx & 127;
        float v = postb[c];
#pragma unroll
        for (int p = 0; p < 8; p++) v += g_part[p][n0 + r][c];
        YsT[c * 20 + r] = v;
    }
    __syncthreads();

    const int w = tid >> 5, lane = tid & 31;
    const int rg = lane >> 2, cp = lane & 3;
    const int c0 = w * 16 + cp * 4;
    const float* wp = mixW + c0;

    ull acc[4] = {0, 0, 0, 0};

#define LOADW4(buf, b)                                                      \
    {                                                                       \
        _Pragma("unroll")                                                   \
        for (int j = 0; j < 4; j++)                                         \
            buf[j] = *(const float4*)(wp + (size_t)((b) * 4 + j) * 128);    \
    }
#define COMP4(b, buf)                                                       \
    {                                                                       \
        _Pragma("unroll")                                                   \
        for (int j = 0; j < 4; j++) {                                       \
            const int k = (b) * 4 + j;                                      \
            ull yv = *(const ull*)&YsT[k * 20 + rg * 2];                    \
            acc[0] = ffma2(yv, dup(buf[j].x), acc[0]);                      \
            acc[1] = ffma2(yv, dup(buf[j].y), acc[1]);                      \
            acc[2] = ffma2(yv, dup(buf[j].z), acc[2]);                      \
            acc[3] = ffma2(yv, dup(buf[j].w), acc[3]);                      \
        }                                                                   \
    }

    float4 wA[4], wB[4];
    LOADW4(wA, 0);
    for (int b = 0; b < 32; b += 2) {
        LOADW4(wB, b + 1);
        COMP4(b, wA);
        if (b + 2 < 32) LOADW4(wA, b + 2);
        COMP4(b + 1, wB);
    }
#undef LOADW4
#undef COMP4

    {
        float lo[4], hi[4];
#pragma unroll
        for (int c = 0; c < 4; c++) {
            unpk(acc[c], lo[c], hi[c]);
            float b = mixb[c0 + c];
            lo[c] += b; hi[c] += b;
            lo[c] = (lo[c] > 0.f) ? lo[c] : 0.01f * lo[c];
            hi[c] = (hi[c] > 0.f) ? hi[c] : 0.01f * hi[c];
        }
        *(float4*)&g_x[(size_t)(n0 + rg * 2) * 128 + c0]     = make_float4(lo[0], lo[1], lo[2], lo[3]);
        *(float4*)&g_x[(size_t)(n0 + rg * 2 + 1) * 128 + c0] = make_float4(hi[0], hi[1], hi[2], hi[3]);
    }
}

// ---------------------------------------------------------------------------
// K5: GRU gate GEMM. grid 96 = 32 rowblocks(64 rows) x 3 gate-colblocks(128).
// S = [X; H] stacked (256 k-rows) transposed in smem. cb 0/1: k 0..255 -> r/z.
// cb 2: phase 0 (k 0..127) -> i_n, phase 1 (k 128..255) -> h_n.
// ---------------------------------------------------------------------------
#define AST2 68
#define SMEM_K5 (256 * AST2 * 4)   // 69632 B

__global__ void __launch_bounds__(256) k5_gru(const float* __restrict__ hidden) {
    extern __shared__ float S[];
    const int tid = threadIdx.x;
    const int w = tid >> 5, lane = tid & 31;
    const int rb = blockIdx.x & 31, cb = blockIdx.x >> 5;
    const int n0 = rb * 64, cg = cb * 128;

    // stage X (k 0..127) and H (k 128..255), transposed
    {
        const int r = tid >> 2, q = tid & 3;
        const float* xs = g_x + (size_t)(n0 + r) * 128 + q * 32;
        const float* hs = hidden + (size_t)(n0 + r) * 128 + q * 32;
#pragma unroll
        for (int i = 0; i < 32; i += 4) {
            float4 v = *(const float4*)(xs + i);
            S[(q * 32 + i + 0) * AST2 + r] = v.x;
            S[(q * 32 + i + 1) * AST2 + r] = v.y;
            S[(q * 32 + i + 2) * AST2 + r] = v.z;
            S[(q * 32 + i + 3) * AST2 + r] = v.w;
        }
#pragma unroll
        for (int i = 0; i < 32; i += 4) {
            float4 v = *(const float4*)(hs + i);
            S[(128 + q * 32 + i + 0) * AST2 + r] = v.x;
            S[(128 + q * 32 + i + 1) * AST2 + r] = v.y;
            S[(128 + q * 32 + i + 2) * AST2 + r] = v.z;
            S[(128 + q * 32 + i + 3) * AST2 + r] = v.w;
        }
    }
    __syncthreads();

    const int rg = lane >> 2, cp = lane & 3;
    const int c0 = w * 16 + cp * 4;
    const int bs = rg * 8;
    const int sel = (rg >= 4) ? 4 : 0;
    const int offA = bs + sel;
    const int offB = bs + 4 - sel;

    const int nph = (cb == 2) ? 2 : 1;
    for (int ph = 0; ph < nph; ph++) {
        const int kb = (cb == 2) ? ph * 128 : 0;
        const int nb = (cb == 2) ? 32 : 64;
        const float* wp = g_WgT + (size_t)kb * 384 + cg + c0;

        ull aA0[4], aA1[4], aB0[4], aB1[4];
#pragma unroll
        for (int c = 0; c < 4; c++) { aA0[c] = 0; aA1[c] = 0; aB0[c] = 0; aB1[c] = 0; }

#define LOADW5(buf, b)                                                      \
    {                                                                       \
        _Pragma("unroll")                                                   \
        for (int j = 0; j < 4; j++)                                         \
            buf[j] = *(const float4*)(wp + (size_t)((b) * 4 + j) * 384);    \
    }
#define COMP5(b, buf)                                                       \
    {                                                                       \
        _Pragma("unroll")                                                   \
        for (int j = 0; j < 4; j++) {                                       \
            const int k = kb + (b) * 4 + j;                                 \
            ulonglong2 A = *(const ulonglong2*)&S[k * AST2 + offA];         \
            ulonglong2 B = *(const ulonglong2*)&S[k * AST2 + offB];         \
            ull w0 = dup(buf[j].x), w1 = dup(buf[j].y);                     \
            ull w2 = dup(buf[j].z), w3 = dup(buf[j].w);                     \
            aA0[0] = ffma2(A.x, w0, aA0[0]); aA0[1] = ffma2(A.x, w1, aA0[1]); \
            aA0[2] = ffma2(A.x, w2, aA0[2]); aA0[3] = ffma2(A.x, w3, aA0[3]); \
            aA1[0] = ffma2(A.y, w0, aA1[0]); aA1[1] = ffma2(A.y, w1, aA1[1]); \
            aA1[2] = ffma2(A.y, w2, aA1[2]); aA1[3] = ffma2(A.y, w3, aA1[3]); \
            aB0[0] = ffma2(B.x, w0, aB0[0]); aB0[1] = ffma2(B.x, w1, aB0[1]); \
            aB0[2] = ffma2(B.x, w2, aB0[2]); aB0[3] = ffma2(B.x, w3, aB0[3]); \
            aB1[0] = ffma2(B.y, w0, aB1[0]); aB1[1] = ffma2(B.y, w1, aB1[1]); \
            aB1[2] = ffma2(B.y, w2, aB1[2]); aB1[3] = ffma2(B.y, w3, aB1[3]); \
        }                                                                   \
    }

        float4 wA[4], wB[4];
        LOADW5(wA, 0);
        for (int b = 0; b < nb; b += 2) {
            LOADW5(wB, b + 1);
            COMP5(b, wA);
            if (b + 2 < nb) LOADW5(wA, b + 2);
            COMP5(b + 1, wB);
        }
#undef LOADW5
#undef COMP5

        // epilogue
        float* P; int st;
        if (cb < 2)       { P = g_gate + cg + c0;  st = 384; }
        else if (ph == 0) { P = g_gate + 256 + c0; st = 384; }
        else              { P = g_gateH + c0;      st = 128; }
        const int rA = n0 + offA, rB = n0 + offB;
        float lo[4], hi[4];
#pragma unroll
        for (int c = 0; c < 4; c++) unpk(aA0[c], lo[c], hi[c]);
        *(float4*)&P[(size_t)(rA + 0) * st] = make_float4(lo[0], lo[1], lo[2], lo[3]);
        *(float4*)&P[(size_t)(rA + 1) * st] = make_float4(hi[0], hi[1], hi[2], hi[3]);
#pragma unroll
        for (int c = 0; c < 4; c++) unpk(aA1[c], lo[c], hi[c]);
        *(float4*)&P[(size_t)(rA + 2) * st] = make_float4(lo[0], lo[1], lo[2], lo[3]);
        *(float4*)&P[(size_t)(rA + 3) * st] = make_float4(hi[0], hi[1], hi[2], hi[3]);
#pragma unroll
        for (int c = 0; c < 4; c++) unpk(aB0[c], lo[c], hi[c]);
        *(float4*)&P[(size_t)(rB + 0) * st] = make_float4(lo[0], lo[1], lo[2], lo[3]);
        *(float4*)&P[(size_t)(rB + 1) * st] = make_float4(hi[0], hi[1], hi[2], hi[3]);
#pragma unroll
        for (int c = 0; c < 4; c++) unpk(aB1[c], lo[c], hi[c]);
        *(float4*)&P[(size_t)(rB + 2) * st] = make_float4(lo[0], lo[1], lo[2], lo[3]);
        *(float4*)&P[(size_t)(rB + 3) * st] = make_float4(hi[0], hi[1], hi[2], hi[3]);
    }
}

// ---------------------------------------------------------------------------
// K6: GRU elementwise epilogue -> out.
// ---------------------------------------------------------------------------
__global__ void __launch_bounds__(256) k6_out(const float* __restrict__ hidden,
                                              float* __restrict__ out) {
    int idx = blockIdx.x * 256 + threadIdx.x;    // 65536 threads x 4 cols
    int r = idx >> 5;
    int c4 = (idx & 31) * 4;
    const float* g = g_gate + (size_t)r * 384;
    float4 rs = *(const float4*)(g + c4);
    float4 zs = *(const float4*)(g + 128 + c4);
    float4 is = *(const float4*)(g + 256 + c4);
    float4 hn = *(const float4*)&g_gateH[(size_t)r * 128 + c4];
    float4 hv = *(const float4*)(hidden + (size_t)r * 128 + c4);
    float o[4];
    float R[4] = {rs.x, rs.y, rs.z, rs.w};
    float Z[4] = {zs.x, zs.y, zs.z, zs.w};
    float I[4] = {is.x, is.y, is.z, is.w};
    float Hn[4] = {hn.x, hn.y, hn.z, hn.w};
    float Hv[4] = {hv.x, hv.y, hv.z, hv.w};
#pragma unroll
    for (int j = 0; j < 4; j++) {
        float rv = 1.f / (1.f + expf(-R[j]));
        float zv = 1.f / (1.f + expf(-Z[j]));
        float nv = tanhf(I[j] + rv * Hn[j]);
        o[j] = (1.f - zv) * nv + zv * Hv[j];
    }
    *(float4*)&out[(size_t)r * 128 + c4] = make_float4(o[0], o[1], o[2], o[3]);
}

// ---------------------------------------------------------------------------
extern "C" void kernel_launch(void* const* d_in, const int* in_sizes, int n_in,
                              void* d_out, int out_size) {
    const float* input  = (const float*)d_in[0];
    const float* adj    = (const float*)d_in[1];
    const float* adjf   = (const float*)d_in[2];
    const float* hidden = (const float*)d_in[3];
    const float* preW   = (const float*)d_in[4];
    const float* preb   = (const float*)d_in[5];
    const float* postW  = (const float*)d_in[6];
    const float* postb  = (const float*)d_in[7];
    const float* mixW   = (const float*)d_in[8];
    const float* mixb   = (const float*)d_in[9];
    const float* Wih    = (const float*)d_in[10];
    const float* Whh    = (const float*)d_in[11];
    float* out = (float*)d_out;

    cudaFuncSetAttribute(k3a_post, cudaFuncAttributeMaxDynamicSharedMemorySize, SMEM_K3A);
    cudaFuncSetAttribute(k5_gru,   cudaFuncAttributeMaxDynamicSharedMemorySize, SMEM_K5);

    k1_hij<<<256, 128>>>(input, preW, Wih, Whh);
    k2_agg<<<BN, 128>>>(adj, adjf, preW, preb);
    k3a_post<<<256, 256, SMEM_K3A>>>(postW);
    k4_mix<<<128, 256>>>(postb, mixW, mixb);
    k5_gru<<<96, 256, SMEM_K5>>>(hidden);
    k6_out<<<256, 256>>>(hidden, out);
}